// round 4
// baseline (speedup 1.0000x reference)
#include <cuda_runtime.h>

#define TT 20000
#define LDP 160

typedef unsigned long long ull;

__device__ __forceinline__ void fma2(ull& d, ull a, ull b) {
    asm("fma.rn.f32x2 %0, %1, %2, %3;" : "=l"(d) : "l"(a), "l"(b), "l"(d));
}
__device__ __forceinline__ float unpack_sum(ull v) {
    return __uint_as_float((unsigned)v) + __uint_as_float((unsigned)(v >> 32));
}

// ---- scratch (static device globals; no allocation) ----
__device__ float g_Ha[(size_t)TT * LDP];   // states @ attn_W1
__device__ float g_Ps[(size_t)TT * LDP];   // states @ sc_W1[0:400]
__device__ float g_Pe[(size_t)TT * LDP];   // states @ sc_W1[400:800]
__device__ float g_PE[(size_t)TT * LDP];   // embeds @ sc_W1[800:1100]
__device__ float g_logit[TT];

struct GemmJobs {
    const float* A[4];
    const float* B[4];
    float*       C[4];
    int          K[4];
    int          lda[4];
};

// C[M,160] = A[M,K] @ B[K,150] (cols 150..159 zero). BM=64, BK=8, 512 thr.
// K-packed fma.rn.f32x2, double-buffered smem. Handles K % 8 != 0.
__global__ __launch_bounds__(512, 2) void proj_gemm(GemmJobs jobs) {
    const int jid = blockIdx.y;
    const float* __restrict__ A = jobs.A[jid];
    const float* __restrict__ B = jobs.B[jid];
    float* __restrict__ C = jobs.C[jid];
    const int K = jobs.K[jid];
    const int lda = jobs.lda[jid];

    __shared__ __align__(16) float As[2][64 * 10];   // [m][kk] stride 10
    __shared__ __align__(16) float Bs[2][160 * 10];  // [j][kk] stride 10

    const int tid = threadIdx.x;
    const int tx = tid & 31;        // col group: cols tx + 32c
    const int ty = tid >> 5;        // row group: rows ty*4 + r
    const int m0 = blockIdx.x * 64;

    ull acc[4][5];
#pragma unroll
    for (int r = 0; r < 4; r++)
#pragma unroll
        for (int c = 0; c < 5; c++) acc[r][c] = 0ull;

    // staging maps (constant across tiles)
    const int aRow = tid >> 3, aK = tid & 7;
    const int aOff = aRow * 10 + aK;
    const bool aOk = (m0 + aRow) < TT;
    const float* aSrc = A + (size_t)(m0 + aRow) * lda + aK;
    int bOff[3]; int bK[3], bJ[3]; bool bOk[3];
#pragma unroll
    for (int i = 0; i < 3; i++) {
        int idx = tid + 512 * i;
        bK[i] = idx / 160; bJ[i] = idx - bK[i] * 160;
        bOk[i] = (idx < 1280) && (bJ[i] < 150);
        bOff[i] = bJ[i] * 10 + bK[i];
    }

    // prologue: stage tile 0 (k-guarded)
    {
        float av = (aOk && aK < K) ? aSrc[0] : 0.f;
        float bv[3];
#pragma unroll
        for (int i = 0; i < 3; i++)
            bv[i] = (bOk[i] && bK[i] < K) ? B[bK[i] * 150 + bJ[i]] : 0.f;
        As[0][aOff] = av;
#pragma unroll
        for (int i = 0; i < 3; i++) if (tid + 512 * i < 1280) Bs[0][bOff[i]] = bv[i];
    }
    __syncthreads();

    const int nt = (K + 7) >> 3;   // handles K=300 (not a multiple of 8)
    for (int t = 0; t < nt; t++) {
        const int cur = t & 1;
        const bool has = (t + 1) < nt;
        float avP = 0.f, bvP[3] = {0.f, 0.f, 0.f};
        if (has) {
            const int k0n = (t + 1) << 3;
            avP = (aOk && k0n + aK < K) ? aSrc[k0n] : 0.f;
#pragma unroll
            for (int i = 0; i < 3; i++)
                bvP[i] = (bOk[i] && k0n + bK[i] < K) ? B[(k0n + bK[i]) * 150 + bJ[i]] : 0.f;
        }
        const float* Asb = As[cur];
        const float* Bsb = Bs[cur];
#pragma unroll
        for (int kp = 0; kp < 4; kp++) {
            ull a2[4];
#pragma unroll
            for (int r = 0; r < 4; r++)
                a2[r] = *(const ull*)(Asb + (ty * 4 + r) * 10 + 2 * kp);
#pragma unroll
            for (int c = 0; c < 5; c++) {
                ull b2 = *(const ull*)(Bsb + (tx + 32 * c) * 10 + 2 * kp);
#pragma unroll
                for (int r = 0; r < 4; r++) fma2(acc[r][c], a2[r], b2);
            }
        }
        if (has) {
            As[cur ^ 1][aOff] = avP;
#pragma unroll
            for (int i = 0; i < 3; i++) if (tid + 512 * i < 1280) Bs[cur ^ 1][bOff[i]] = bvP[i];
        }
        __syncthreads();
    }

#pragma unroll
    for (int r = 0; r < 4; r++) {
        int m = m0 + ty * 4 + r;
        if (m < TT) {
#pragma unroll
            for (int c = 0; c < 5; c++)
                C[(size_t)m * LDP + tx + 32 * c] = unpack_sum(acc[r][c]);
        }
    }
}

// Attention MLP tail: logit[t] = relu(relu(Ha+b1) @ W2 + b2) . W3 + b3
// 64 tokens/block, 512 thr, k-packed FMA2, W2 transposed (stride 154).
__global__ __launch_bounds__(512, 1) void attn_tail(
    const float* __restrict__ b1, const float* __restrict__ W2,
    const float* __restrict__ b2, const float* __restrict__ W3,
    const float* __restrict__ b3) {
    extern __shared__ __align__(16) float sm[];
    float* W2T = sm;                 // 160*154, [j][k]
    float* W3s = W2T + 160 * 154;    // 160
    float* b2s = W3s + 160;          // 160
    float* h1s = b2s + 160;          // 64*154, [t][k]

    const int tid = threadIdx.x;
    for (int i = tid; i < 160 * 154; i += 512) W2T[i] = 0.f;
    if (tid < 160) {
        W3s[tid] = (tid < 150) ? W3[tid] : 0.f;
        b2s[tid] = (tid < 150) ? b2[tid] : 0.f;
    }
    __syncthreads();
    for (int i = tid; i < 22500; i += 512) {
        int k = i / 150, j = i - k * 150;
        W2T[j * 154 + k] = W2[i];
    }

    const int t0 = blockIdx.x * 64;
    for (int idx = tid; idx < 64 * 150; idx += 512) {
        int t = idx / 150, k = idx - t * 150;
        float v = 0.f;
        if (t0 + t < TT) v = fmaxf(g_Ha[(size_t)(t0 + t) * LDP + k] + b1[k], 0.f);
        h1s[t * 154 + k] = v;
    }
    __syncthreads();

    const int w = tid >> 5, lane = tid & 31;
    ull acc[4][5];
#pragma unroll
    for (int i = 0; i < 4; i++)
#pragma unroll
        for (int c = 0; c < 5; c++) acc[i][c] = 0ull;

    for (int kp = 0; kp < 75; kp++) {
        ull h2[4];
#pragma unroll
        for (int i = 0; i < 4; i++)
            h2[i] = *(const ull*)(h1s + (w * 4 + i) * 154 + 2 * kp);
#pragma unroll
        for (int c = 0; c < 5; c++) {
            ull b2v = *(const ull*)(W2T + (lane + 32 * c) * 154 + 2 * kp);
#pragma unroll
            for (int i = 0; i < 4; i++) fma2(acc[i][c], h2[i], b2v);
        }
    }
#pragma unroll
    for (int i = 0; i < 4; i++) {
        float p = 0.f;
#pragma unroll
        for (int c = 0; c < 5; c++) {
            int j = lane + 32 * c;
            if (j < 150) p += fmaxf(unpack_sum(acc[i][c]) + b2s[j], 0.f) * W3s[j];
        }
#pragma unroll
        for (int off = 16; off > 0; off >>= 1) p += __shfl_xor_sync(0xffffffffu, p, off);
        int t = w * 4 + i;
        if (lane == 0 && t0 + t < TT) g_logit[t0 + t] = p + b3[0];
    }
}

// Span scorer: persistent, 64 spans/tile, k-packed FMA2 layer-2.
__global__ __launch_bounds__(512, 1) void span_score(
    const float* __restrict__ b1, const float* __restrict__ W2,
    const float* __restrict__ b2, const float* __restrict__ W3,
    const float* __restrict__ b3, float* __restrict__ out, int totalTiles) {
    extern __shared__ __align__(16) float sm[];
    float* W2T = sm;                 // 160*154
    float* W3s = W2T + 160 * 154;    // 160
    float* b2s = W3s + 160;          // 160
    float* b1s = b2s + 160;          // 160
    float* h1s = b1s + 160;          // 64*154
    float* PEs = h1s + 64 * 154;     // 73*150
    float* ws  = PEs + 73 * 150;     // 64*10

    const int tid = threadIdx.x;
    for (int i = tid; i < 160 * 154; i += 512) W2T[i] = 0.f;
    if (tid < 160) {
        W3s[tid] = (tid < 150) ? W3[tid] : 0.f;
        b2s[tid] = (tid < 150) ? b2[tid] : 0.f;
        b1s[tid] = (tid < 150) ? b1[tid] : 0.f;
    }
    __syncthreads();
    for (int i = tid; i < 22500; i += 512) {
        int k = i / 150, j = i - k * 150;
        W2T[j * 154 + k] = W2[i];
    }
    const float bias3 = b3[0];
    const int w = tid >> 5, lane = tid & 31;

    for (int tile = blockIdx.x; tile < totalTiles; tile += gridDim.x) {
        int n = 1, loc = tile;
#pragma unroll
        for (int nn = 1; nn <= 10; nn++) {
            int tn = (TT - nn + 1 + 63) >> 6;
            if (loc < tn) { n = nn; break; }
            loc -= tn;
        }
        const int s0 = loc << 6;
        const int S = TT - n + 1;
        const int cnt = min(64, S - s0);

        __syncthreads();  // previous tile's readers done

        // stage PE rows [s0 .. s0+cnt+8] (always cnt+9 rows; OOB -> 0)
        const int rows = cnt + 9;
        for (int idx = tid; idx < rows * 150; idx += 512) {
            int r = idx / 150, k = idx - r * 150;
            PEs[idx] = (s0 + r < TT) ? g_PE[(size_t)(s0 + r) * LDP + k] : 0.f;
        }
        // softmax weights, zero-padded to width 10
        if (tid < 64) {
            float l[10];
            if (tid < cnt) {
                int s = s0 + tid;
                float m = -1e30f;
                for (int j = 0; j < n; j++) { l[j] = g_logit[s + j]; m = fmaxf(m, l[j]); }
                float sum = 0.f;
                for (int j = 0; j < n; j++) { l[j] = expf(l[j] - m); sum += l[j]; }
                float inv = 1.f / sum;
#pragma unroll
                for (int j = 0; j < 10; j++) ws[tid * 10 + j] = (j < n) ? l[j] * inv : 0.f;
            } else {
#pragma unroll
                for (int j = 0; j < 10; j++) ws[tid * 10 + j] = 0.f;
            }
        }
        __syncthreads();

        // h1 = relu(Ps + Pe + b1 + pooled PE), fully unrolled width-10 pooling
        for (int idx = tid; idx < 64 * 150; idx += 512) {
            int t = idx / 150, k = idx - t * 150;
            float a = 0.f;
            if (t < cnt) {
                int s = s0 + t;
                a = g_Ps[(size_t)s * LDP + k] + g_Pe[(size_t)(s + n - 1) * LDP + k] + b1s[k];
#pragma unroll
                for (int j = 0; j < 10; j++)
                    a = fmaf(ws[t * 10 + j], PEs[(t + j) * 150 + k], a);
                a = fmaxf(a, 0.f);
            }
            h1s[t * 154 + k] = a;
        }
        __syncthreads();

        // layer 2 (150x150, k-packed FMA2) + layer 3
        ull acc[4][5];
#pragma unroll
        for (int i = 0; i < 4; i++)
#pragma unroll
            for (int c = 0; c < 5; c++) acc[i][c] = 0ull;

        for (int kp = 0; kp < 75; kp++) {
            ull h2[4];
#pragma unroll
            for (int i = 0; i < 4; i++)
                h2[i] = *(const ull*)(h1s + (w * 4 + i) * 154 + 2 * kp);
#pragma unroll
            for (int c = 0; c < 5; c++) {
                ull b2v = *(const ull*)(W2T + (lane + 32 * c) * 154 + 2 * kp);
#pragma unroll
                for (int i = 0; i < 4; i++) fma2(acc[i][c], h2[i], b2v);
            }
        }
        const int base = (n - 1) * TT - ((n - 1) * (n - 2)) / 2;
#pragma unroll
        for (int i = 0; i < 4; i++) {
            float p = 0.f;
#pragma unroll
            for (int c = 0; c < 5; c++) {
                int j = lane + 32 * c;
                if (j < 150) p += fmaxf(unpack_sum(acc[i][c]) + b2s[j], 0.f) * W3s[j];
            }
#pragma unroll
            for (int off = 16; off > 0; off >>= 1) p += __shfl_xor_sync(0xffffffffu, p, off);
            int t = w * 4 + i;
            if (lane == 0 && t < cnt) out[base + s0 + t] = p + bias3;
        }
    }
}

extern "C" void kernel_launch(void* const* d_in, const int* in_sizes, int n_in,
                              void* d_out, int out_size) {
    const float* embeds  = (const float*)d_in[0];
    const float* states  = (const float*)d_in[1];
    const float* attn_W1 = (const float*)d_in[2];
    const float* attn_b1 = (const float*)d_in[3];
    const float* attn_W2 = (const float*)d_in[4];
    const float* attn_b2 = (const float*)d_in[5];
    const float* attn_W3 = (const float*)d_in[6];
    const float* attn_b3 = (const float*)d_in[7];
    const float* sc_W1   = (const float*)d_in[8];
    const float* sc_b1   = (const float*)d_in[9];
    const float* sc_W2   = (const float*)d_in[10];
    const float* sc_b2   = (const float*)d_in[11];
    const float* sc_W3   = (const float*)d_in[12];
    const float* sc_b3   = (const float*)d_in[13];
    float* out = (float*)d_out;

    float *pHa, *pPs, *pPe, *pPE;
    cudaGetSymbolAddress((void**)&pHa, g_Ha);
    cudaGetSymbolAddress((void**)&pPs, g_Ps);
    cudaGetSymbolAddress((void**)&pPe, g_Pe);
    cudaGetSymbolAddress((void**)&pPE, g_PE);

    GemmJobs jobs;
    jobs.A[0] = states; jobs.B[0] = attn_W1;            jobs.C[0] = pHa; jobs.K[0] = 400; jobs.lda[0] = 400;
    jobs.A[1] = states; jobs.B[1] = sc_W1;              jobs.C[1] = pPs; jobs.K[1] = 400; jobs.lda[1] = 400;
    jobs.A[2] = states; jobs.B[2] = sc_W1 + 400 * 150;  jobs.C[2] = pPe; jobs.K[2] = 400; jobs.lda[2] = 400;
    jobs.A[3] = embeds; jobs.B[3] = sc_W1 + 800 * 150;  jobs.C[3] = pPE; jobs.K[3] = 300; jobs.lda[3] = 300;

    const int attnSmem = (160 * 154 + 160 + 160 + 64 * 154) * 4;
    const int spanSmem = (160 * 154 + 160 * 3 + 64 * 154 + 73 * 150 + 640) * 4;
    cudaFuncSetAttribute(attn_tail, cudaFuncAttributeMaxDynamicSharedMemorySize, attnSmem);
    cudaFuncSetAttribute(span_score, cudaFuncAttributeMaxDynamicSharedMemorySize, spanSmem);

    int totalTiles = 0;
    for (int nn = 1; nn <= 10; nn++) totalTiles += (TT - nn + 1 + 63) >> 6;

    proj_gemm<<<dim3((TT + 63) / 64, 4), 512>>>(jobs);
    attn_tail<<<(TT + 63) / 64, 512, attnSmem>>>(attn_b1, attn_W2, attn_b2, attn_W3, attn_b3);
    span_score<<<148, 512, spanSmem>>>(sc_b1, sc_W2, sc_b2, sc_W3, sc_b3, out, totalTiles);
}

// round 5
// speedup vs baseline: 1.2352x; 1.2352x over previous
#include <cuda_runtime.h>

#define TT 20000
#define LDP 160

typedef unsigned long long ull;

__device__ __forceinline__ void fma2(ull& d, ull a, ull b) {
    asm("fma.rn.f32x2 %0, %1, %2, %3;" : "=l"(d) : "l"(a), "l"(b), "l"(d));
}
__device__ __forceinline__ float unpack_sum(ull v) {
    return __uint_as_float((unsigned)v) + __uint_as_float((unsigned)(v >> 32));
}
__device__ __forceinline__ float lo32(ull v) { return __uint_as_float((unsigned)v); }
__device__ __forceinline__ float hi32(ull v) { return __uint_as_float((unsigned)(v >> 32)); }
__device__ __forceinline__ ull pack2(float a, float b) {
    ull r;
    asm("mov.b64 %0, {%1, %2};" : "=l"(r) : "f"(a), "f"(b));
    return r;
}

// ---- scratch (static device globals; no allocation) ----
__device__ float g_Ha[(size_t)TT * LDP];   // states @ attn_W1
__device__ float g_Ps[(size_t)TT * LDP];   // states @ sc_W1[0:400]
__device__ float g_Pe[(size_t)TT * LDP];   // states @ sc_W1[400:800]
__device__ float g_PE[(size_t)TT * LDP];   // embeds @ sc_W1[800:1100]
__device__ float g_logit[TT];

struct GemmJobs {
    const float* A[4];
    const float* B[4];
    float*       C[4];
    int          K[4];
    int          lda[4];
};

// C[M,160] = A[M,K] @ B[K,150] (cols 150..159 zero). BM=128, BK=8, 256 thr.
// M-packed fma.rn.f32x2: 8 rows (4 pairs) x 10 cols per thread.
// As transposed [kk][m] (pair-contiguous), Bs duplicated (b,b) pairs.
__global__ __launch_bounds__(256, 2) void proj_gemm(GemmJobs jobs) {
    const int jid = blockIdx.y;
    const float* __restrict__ A = jobs.A[jid];
    const float* __restrict__ B = jobs.B[jid];
    float* __restrict__ C = jobs.C[jid];
    const int K = jobs.K[jid];
    const int lda = jobs.lda[jid];

    __shared__ __align__(16) float As[2][8 * 132];    // [kk][m], row stride 132
    __shared__ __align__(16) float Bs[2][8 * 320];    // [kk][2j] duplicated pairs

    const int tid = threadIdx.x;
    const int tx = tid & 15;        // col group: cols tx + 16c
    const int ty = tid >> 4;        // row group: rows ty*8 .. ty*8+7
    const int m0 = blockIdx.x * 128;

    ull acc[4][10];
#pragma unroll
    for (int p = 0; p < 4; p++)
#pragma unroll
        for (int c = 0; c < 10; c++) acc[p][c] = 0ull;

    // staging maps
    const int aRow = tid >> 1;      // 0..127
    const int aU = tid & 1;         // k-half: 0 -> kk 0..3, 1 -> kk 4..7
    const bool aOk = (m0 + aRow) < TT;
    const float* aSrc = A + (size_t)(m0 + aRow) * lda + aU * 4;
    int bK[5], bJ[5]; bool bOk[5];
#pragma unroll
    for (int i = 0; i < 5; i++) {
        int idx = tid + 256 * i;    // 0..1279 exactly
        bK[i] = idx / 160; bJ[i] = idx - bK[i] * 160;
        bOk[i] = (bJ[i] < 150);
    }

    // prologue: stage tile 0 (k-guarded; K is a multiple of 4, so float4 ok)
    {
        float4 av = make_float4(0.f, 0.f, 0.f, 0.f);
        if (aOk && aU * 4 < K) av = *(const float4*)aSrc;
        float bv[5];
#pragma unroll
        for (int i = 0; i < 5; i++)
            bv[i] = (bOk[i] && bK[i] < K) ? B[bK[i] * 150 + bJ[i]] : 0.f;
        As[0][(aU * 4 + 0) * 132 + aRow] = av.x;
        As[0][(aU * 4 + 1) * 132 + aRow] = av.y;
        As[0][(aU * 4 + 2) * 132 + aRow] = av.z;
        As[0][(aU * 4 + 3) * 132 + aRow] = av.w;
#pragma unroll
        for (int i = 0; i < 5; i++)
            *(ull*)(&Bs[0][bK[i] * 320 + 2 * bJ[i]]) = pack2(bv[i], bv[i]);
    }
    __syncthreads();

    const int nt = (K + 7) >> 3;
    for (int t = 0; t < nt; t++) {
        const int cur = t & 1;
        const bool has = (t + 1) < nt;
        float4 avP = make_float4(0.f, 0.f, 0.f, 0.f);
        float bvP[5] = {0.f, 0.f, 0.f, 0.f, 0.f};
        if (has) {
            const int k0n = (t + 1) << 3;
            if (aOk && k0n + aU * 4 < K) avP = *(const float4*)(aSrc + k0n);
#pragma unroll
            for (int i = 0; i < 5; i++)
                bvP[i] = (bOk[i] && k0n + bK[i] < K) ? B[(k0n + bK[i]) * 150 + bJ[i]] : 0.f;
        }
        const float* Asb = As[cur];
        const float* Bsb = Bs[cur];
#pragma unroll
        for (int kk = 0; kk < 8; kk++) {
            ull a2[4];
#pragma unroll
            for (int p = 0; p < 4; p++)
                a2[p] = *(const ull*)(Asb + kk * 132 + ty * 8 + 2 * p);
            ull b2[10];
#pragma unroll
            for (int c = 0; c < 10; c++)
                b2[c] = *(const ull*)(Bsb + kk * 320 + 2 * (tx + 16 * c));
#pragma unroll
            for (int p = 0; p < 4; p++)
#pragma unroll
                for (int c = 0; c < 10; c++) fma2(acc[p][c], a2[p], b2[c]);
        }
        if (has) {
            As[cur ^ 1][(aU * 4 + 0) * 132 + aRow] = avP.x;
            As[cur ^ 1][(aU * 4 + 1) * 132 + aRow] = avP.y;
            As[cur ^ 1][(aU * 4 + 2) * 132 + aRow] = avP.z;
            As[cur ^ 1][(aU * 4 + 3) * 132 + aRow] = avP.w;
#pragma unroll
            for (int i = 0; i < 5; i++)
                *(ull*)(&Bs[cur ^ 1][bK[i] * 320 + 2 * bJ[i]]) = pack2(bvP[i], bvP[i]);
        }
        __syncthreads();
    }

#pragma unroll
    for (int p = 0; p < 4; p++) {
        int m = m0 + ty * 8 + 2 * p;
        if (m < TT) {
#pragma unroll
            for (int c = 0; c < 10; c++)
                C[(size_t)m * LDP + tx + 16 * c] = lo32(acc[p][c]);
        }
        if (m + 1 < TT) {
#pragma unroll
            for (int c = 0; c < 10; c++)
                C[(size_t)(m + 1) * LDP + tx + 16 * c] = hi32(acc[p][c]);
        }
    }
}

// Attention MLP tail: logit[t] = relu(relu(Ha+b1) @ W2 + b2) . W3 + b3
// 64 tokens/block, 512 thr, k-packed FMA2, W2 transposed (stride 154).
__global__ __launch_bounds__(512, 1) void attn_tail(
    const float* __restrict__ b1, const float* __restrict__ W2,
    const float* __restrict__ b2, const float* __restrict__ W3,
    const float* __restrict__ b3) {
    extern __shared__ __align__(16) float sm[];
    float* W2T = sm;                 // 160*154, [j][k]
    float* W3s = W2T + 160 * 154;    // 160
    float* b2s = W3s + 160;          // 160
    float* h1s = b2s + 160;          // 64*154, [t][k]

    const int tid = threadIdx.x;
    for (int i = tid; i < 160 * 154; i += 512) W2T[i] = 0.f;
    if (tid < 160) {
        W3s[tid] = (tid < 150) ? W3[tid] : 0.f;
        b2s[tid] = (tid < 150) ? b2[tid] : 0.f;
    }
    __syncthreads();
    for (int i = tid; i < 22500; i += 512) {
        int k = i / 150, j = i - k * 150;
        W2T[j * 154 + k] = W2[i];
    }

    const int t0 = blockIdx.x * 64;
    for (int idx = tid; idx < 64 * 150; idx += 512) {
        int t = idx / 150, k = idx - t * 150;
        float v = 0.f;
        if (t0 + t < TT) v = fmaxf(g_Ha[(size_t)(t0 + t) * LDP + k] + b1[k], 0.f);
        h1s[t * 154 + k] = v;
    }
    __syncthreads();

    const int w = tid >> 5, lane = tid & 31;
    ull acc[4][5];
#pragma unroll
    for (int i = 0; i < 4; i++)
#pragma unroll
        for (int c = 0; c < 5; c++) acc[i][c] = 0ull;

#pragma unroll 5
    for (int kp = 0; kp < 75; kp++) {
        ull h2[4];
#pragma unroll
        for (int i = 0; i < 4; i++)
            h2[i] = *(const ull*)(h1s + (w * 4 + i) * 154 + 2 * kp);
#pragma unroll
        for (int c = 0; c < 5; c++) {
            ull b2v = *(const ull*)(W2T + (lane + 32 * c) * 154 + 2 * kp);
#pragma unroll
            for (int i = 0; i < 4; i++) fma2(acc[i][c], h2[i], b2v);
        }
    }
#pragma unroll
    for (int i = 0; i < 4; i++) {
        float p = 0.f;
#pragma unroll
        for (int c = 0; c < 5; c++) {
            int j = lane + 32 * c;
            if (j < 150) p += fmaxf(unpack_sum(acc[i][c]) + b2s[j], 0.f) * W3s[j];
        }
#pragma unroll
        for (int off = 16; off > 0; off >>= 1) p += __shfl_xor_sync(0xffffffffu, p, off);
        int t = w * 4 + i;
        if (lane == 0 && t0 + t < TT) g_logit[t0 + t] = p + b3[0];
    }
}

// Span scorer: persistent, 64 spans/tile, k-packed FMA2 layer-2.
__global__ __launch_bounds__(512, 1) void span_score(
    const float* __restrict__ b1, const float* __restrict__ W2,
    const float* __restrict__ b2, const float* __restrict__ W3,
    const float* __restrict__ b3, float* __restrict__ out, int totalTiles) {
    extern __shared__ __align__(16) float sm[];
    float* W2T = sm;                 // 160*154
    float* W3s = W2T + 160 * 154;    // 160
    float* b2s = W3s + 160;          // 160
    float* b1s = b2s + 160;          // 160
    float* h1s = b1s + 160;          // 64*154
    float* PEs = h1s + 64 * 154;     // 73*150
    float* ws  = PEs + 73 * 150;     // 64*10

    const int tid = threadIdx.x;
    for (int i = tid; i < 160 * 154; i += 512) W2T[i] = 0.f;
    if (tid < 160) {
        W3s[tid] = (tid < 150) ? W3[tid] : 0.f;
        b2s[tid] = (tid < 150) ? b2[tid] : 0.f;
        b1s[tid] = (tid < 150) ? b1[tid] : 0.f;
    }
    __syncthreads();
    for (int i = tid; i < 22500; i += 512) {
        int k = i / 150, j = i - k * 150;
        W2T[j * 154 + k] = W2[i];
    }
    const float bias3 = b3[0];
    const int w = tid >> 5, lane = tid & 31;

    for (int tile = blockIdx.x; tile < totalTiles; tile += gridDim.x) {
        int n = 1, loc = tile;
#pragma unroll
        for (int nn = 1; nn <= 10; nn++) {
            int tn = (TT - nn + 1 + 63) >> 6;
            if (loc < tn) { n = nn; break; }
            loc -= tn;
        }
        const int s0 = loc << 6;
        const int S = TT - n + 1;
        const int cnt = min(64, S - s0);

        __syncthreads();  // previous tile's readers done

        // stage PE rows [s0 .. s0+cnt+8] (always cnt+9 rows; OOB -> 0)
        const int rows = cnt + 9;
        for (int idx = tid; idx < rows * 150; idx += 512) {
            int r = idx / 150, k = idx - r * 150;
            PEs[idx] = (s0 + r < TT) ? g_PE[(size_t)(s0 + r) * LDP + k] : 0.f;
        }
        // softmax weights, zero-padded to width 10
        if (tid < 64) {
            float l[10];
            if (tid < cnt) {
                int s = s0 + tid;
                float m = -1e30f;
                for (int j = 0; j < n; j++) { l[j] = g_logit[s + j]; m = fmaxf(m, l[j]); }
                float sum = 0.f;
                for (int j = 0; j < n; j++) { l[j] = expf(l[j] - m); sum += l[j]; }
                float inv = 1.f / sum;
#pragma unroll
                for (int j = 0; j < 10; j++) ws[tid * 10 + j] = (j < n) ? l[j] * inv : 0.f;
            } else {
#pragma unroll
                for (int j = 0; j < 10; j++) ws[tid * 10 + j] = 0.f;
            }
        }
        __syncthreads();

        // h1 = relu(Ps + Pe + b1 + pooled PE), fully unrolled width-10 pooling
        for (int idx = tid; idx < 64 * 150; idx += 512) {
            int t = idx / 150, k = idx - t * 150;
            float a = 0.f;
            if (t < cnt) {
                int s = s0 + t;
                a = g_Ps[(size_t)s * LDP + k] + g_Pe[(size_t)(s + n - 1) * LDP + k] + b1s[k];
#pragma unroll
                for (int j = 0; j < 10; j++)
                    a = fmaf(ws[t * 10 + j], PEs[(t + j) * 150 + k], a);
                a = fmaxf(a, 0.f);
            }
            h1s[t * 154 + k] = a;
        }
        __syncthreads();

        // layer 2 (150x150, k-packed FMA2) + layer 3
        ull acc[4][5];
#pragma unroll
        for (int i = 0; i < 4; i++)
#pragma unroll
            for (int c = 0; c < 5; c++) acc[i][c] = 0ull;

#pragma unroll 5
        for (int kp = 0; kp < 75; kp++) {
            ull h2[4];
#pragma unroll
            for (int i = 0; i < 4; i++)
                h2[i] = *(const ull*)(h1s + (w * 4 + i) * 154 + 2 * kp);
#pragma unroll
            for (int c = 0; c < 5; c++) {
                ull b2v = *(const ull*)(W2T + (lane + 32 * c) * 154 + 2 * kp);
#pragma unroll
                for (int i = 0; i < 4; i++) fma2(acc[i][c], h2[i], b2v);
            }
        }
        const int base = (n - 1) * TT - ((n - 1) * (n - 2)) / 2;
#pragma unroll
        for (int i = 0; i < 4; i++) {
            float p = 0.f;
#pragma unroll
            for (int c = 0; c < 5; c++) {
                int j = lane + 32 * c;
                if (j < 150) p += fmaxf(unpack_sum(acc[i][c]) + b2s[j], 0.f) * W3s[j];
            }
#pragma unroll
            for (int off = 16; off > 0; off >>= 1) p += __shfl_xor_sync(0xffffffffu, p, off);
            int t = w * 4 + i;
            if (lane == 0 && t < cnt) out[base + s0 + t] = p + bias3;
        }
    }
}

extern "C" void kernel_launch(void* const* d_in, const int* in_sizes, int n_in,
                              void* d_out, int out_size) {
    const float* embeds  = (const float*)d_in[0];
    const float* states  = (const float*)d_in[1];
    const float* attn_W1 = (const float*)d_in[2];
    const float* attn_b1 = (const float*)d_in[3];
    const float* attn_W2 = (const float*)d_in[4];
    const float* attn_b2 = (const float*)d_in[5];
    const float* attn_W3 = (const float*)d_in[6];
    const float* attn_b3 = (const float*)d_in[7];
    const float* sc_W1   = (const float*)d_in[8];
    const float* sc_b1   = (const float*)d_in[9];
    const float* sc_W2   = (const float*)d_in[10];
    const float* sc_b2   = (const float*)d_in[11];
    const float* sc_W3   = (const float*)d_in[12];
    const float* sc_b3   = (const float*)d_in[13];
    float* out = (float*)d_out;

    float *pHa, *pPs, *pPe, *pPE;
    cudaGetSymbolAddress((void**)&pHa, g_Ha);
    cudaGetSymbolAddress((void**)&pPs, g_Ps);
    cudaGetSymbolAddress((void**)&pPe, g_Pe);
    cudaGetSymbolAddress((void**)&pPE, g_PE);

    GemmJobs jobs;
    jobs.A[0] = states; jobs.B[0] = attn_W1;            jobs.C[0] = pHa; jobs.K[0] = 400; jobs.lda[0] = 400;
    jobs.A[1] = states; jobs.B[1] = sc_W1;              jobs.C[1] = pPs; jobs.K[1] = 400; jobs.lda[1] = 400;
    jobs.A[2] = states; jobs.B[2] = sc_W1 + 400 * 150;  jobs.C[2] = pPe; jobs.K[2] = 400; jobs.lda[2] = 400;
    jobs.A[3] = embeds; jobs.B[3] = sc_W1 + 800 * 150;  jobs.C[3] = pPE; jobs.K[3] = 300; jobs.lda[3] = 300;

    const int attnSmem = (160 * 154 + 160 + 160 + 64 * 154) * 4;
    const int spanSmem = (160 * 154 + 160 * 3 + 64 * 154 + 73 * 150 + 640) * 4;
    cudaFuncSetAttribute(attn_tail, cudaFuncAttributeMaxDynamicSharedMemorySize, attnSmem);
    cudaFuncSetAttribute(span_score, cudaFuncAttributeMaxDynamicSharedMemorySize, spanSmem);

    int totalTiles = 0;
    for (int nn = 1; nn <= 10; nn++) totalTiles += (TT - nn + 1 + 63) >> 6;

    proj_gemm<<<dim3((TT + 127) / 128, 4), 256>>>(jobs);
    attn_tail<<<(TT + 63) / 64, 512, attnSmem>>>(attn_b1, attn_W2, attn_b2, attn_W3, attn_b3);
    span_score<<<148, 512, spanSmem>>>(sc_b1, sc_W2, sc_b2, sc_W3, sc_b3, out, totalTiles);
}

// round 12
// speedup vs baseline: 1.2368x; 1.0013x over previous
#include <cuda_runtime.h>

#define TT 20000
#define LDP 160

typedef unsigned long long ull;
typedef unsigned uns;

__device__ __forceinline__ void fma2(ull& d, ull a, ull b) {
    asm("fma.rn.f32x2 %0, %1, %2, %3;" : "=l"(d) : "l"(a), "l"(b), "l"(d));
}
__device__ __forceinline__ float unpack_sum(ull v) {
    return __uint_as_float((uns)v) + __uint_as_float((uns)(v >> 32));
}

// ---- scratch (static device globals; no allocation) ----
__device__ float g_Ha[(size_t)TT * LDP];
__device__ float g_Ps[(size_t)TT * LDP];
__device__ float g_Pe[(size_t)TT * LDP];
__device__ float g_PE[(size_t)TT * LDP];
__device__ float g_logit[TT];

// ---- bf16 mma.sync (base sm_80+ feature, works on sm_103 target) ----
__device__ __forceinline__ void mma16816(float& c0, float& c1, float& c2, float& c3,
                                         uns a0, uns a1, uns a2, uns a3,
                                         uns b0, uns b1) {
    asm volatile("mma.sync.aligned.m16n8k16.row.col.f32.bf16.bf16.f32 {%0,%1,%2,%3}, {%4,%5,%6,%7}, {%8,%9}, {%0,%1,%2,%3};" : "+f"(c0), "+f"(c1), "+f"(c2), "+f"(c3) : "r"(a0), "r"(a1), "r"(a2), "r"(a3), "r"(b0), "r"(b1));
}

// smem layout for proj_mma (bytes): padded stride 72 bf16 per row
#define PJ_AH 0
#define PJ_AL 9216
#define PJ_BH 18432
#define PJ_BL 41472
#define PJ_SMEM 64512

// C[M,160] = A[M,K] @ B[K,150] via warp mma.sync bf16 hi/lo (3 terms).
// Block: 256 thr = 8 warps; tile 64 rows x 160 cols; K chunks of 64.
__global__ __launch_bounds__(256, 2) void proj_mma(const float* __restrict__ A,
                                                   const float* __restrict__ B,
                                                   float* __restrict__ C,
                                                   int K, int lda) {
    extern __shared__ __align__(16) char smc[];
    const int tid = threadIdx.x;
    const int m0 = blockIdx.x * 64;
    const int warp = tid >> 5;
    const int lane = tid & 31;
    const int gid = lane >> 2;       // group id 0..7
    const int tig = lane & 3;        // thread in group
    const int mw = warp & 3;         // m-tile 0..3 (rows mw*16..+15)
    const int nh = warp >> 2;        // n-half 0..1 (cols nh*80..+79)

    float acc[10][4];
#pragma unroll
    for (int j = 0; j < 10; j++) {
#pragma unroll
        for (int q = 0; q < 4; q++) acc[j][q] = 0.f;
    }

    const int nt = (K + 63) >> 6;
    for (int t = 0; t < nt; t++) {
        const int k0 = t << 6;
        __syncthreads();   // protect previous chunk's readers
        // stage A: 64 rows x 32 k-pairs, bf16 hi/lo packed pairs
        for (int idx = tid; idx < 2048; idx += 256) {
            int row = idx >> 5;
            int kp = idx & 31;
            int k = k0 + kp * 2;
            float2 v = make_float2(0.f, 0.f);
            if (m0 + row < TT && k < K)
                v = *(const float2*)(A + (size_t)(m0 + row) * lda + k);
            uns ux = __float_as_uint(v.x);
            uns uy = __float_as_uint(v.y);
            uns hx = ux & 0xFFFF0000u;
            uns hy = uy & 0xFFFF0000u;
            float rx = v.x - __uint_as_float(hx);
            float ry = v.y - __uint_as_float(hy);
            uns hip = (hx >> 16) | (hy & 0xFFFF0000u);
            uns lop = (__float_as_uint(rx) >> 16) | (__float_as_uint(ry) & 0xFFFF0000u);
            int boff = (row * 72 + kp * 2) * 2;
            *(uns*)(smc + PJ_AH + boff) = hip;
            *(uns*)(smc + PJ_AL + boff) = lop;
        }
        // stage B transposed: smem [n][k], 160 n x 64 k, bf16 hi/lo
        for (int idx = tid; idx < 10240; idx += 256) {
            int kk = idx / 160;
            int n = idx - kk * 160;
            float v = 0.f;
            if (n < 150 && k0 + kk < K) v = B[(k0 + kk) * 150 + n];
            uns u = __float_as_uint(v);
            uns h = u & 0xFFFF0000u;
            float r = v - __uint_as_float(h);
            int boff = (n * 72 + kk) * 2;
            *(unsigned short*)(smc + PJ_BH + boff) = (unsigned short)(h >> 16);
            *(unsigned short*)(smc + PJ_BL + boff) = (unsigned short)(__float_as_uint(r) >> 16);
        }
        __syncthreads();

#pragma unroll
        for (int ks = 0; ks < 4; ks++) {
            // A fragments for this warp's m-tile (hi and lo)
            int arow0 = (mw * 16 + gid) * 72;
            int acol = ks * 16 + tig * 2;
            uns ah0 = *(uns*)(smc + PJ_AH + (arow0 + acol) * 2);
            uns ah1 = *(uns*)(smc + PJ_AH + (arow0 + 8 * 72 + acol) * 2);
            uns ah2 = *(uns*)(smc + PJ_AH + (arow0 + acol + 8) * 2);
            uns ah3 = *(uns*)(smc + PJ_AH + (arow0 + 8 * 72 + acol + 8) * 2);
            uns al0 = *(uns*)(smc + PJ_AL + (arow0 + acol) * 2);
            uns al1 = *(uns*)(smc + PJ_AL + (arow0 + 8 * 72 + acol) * 2);
            uns al2 = *(uns*)(smc + PJ_AL + (arow0 + acol + 8) * 2);
            uns al3 = *(uns*)(smc + PJ_AL + (arow0 + 8 * 72 + acol + 8) * 2);
#pragma unroll
            for (int j = 0; j < 10; j++) {
                int n = (nh * 10 + j) * 8 + gid;
                int kc = ks * 16 + tig * 2;
                uns bh0 = *(uns*)(smc + PJ_BH + (n * 72 + kc) * 2);
                uns bh1 = *(uns*)(smc + PJ_BH + (n * 72 + kc + 8) * 2);
                uns bl0 = *(uns*)(smc + PJ_BL + (n * 72 + kc) * 2);
                uns bl1 = *(uns*)(smc + PJ_BL + (n * 72 + kc + 8) * 2);
                mma16816(acc[j][0], acc[j][1], acc[j][2], acc[j][3], ah0, ah1, ah2, ah3, bh0, bh1);
                mma16816(acc[j][0], acc[j][1], acc[j][2], acc[j][3], ah0, ah1, ah2, ah3, bl0, bl1);
                mma16816(acc[j][0], acc[j][1], acc[j][2], acc[j][3], al0, al1, al2, al3, bh0, bh1);
            }
        }
    }

    // epilogue: c0,c1 -> row m0+mw*16+gid, cols col..col+1; c2,c3 -> row+8
    {
        int mA = m0 + mw * 16 + gid;
        int mB = mA + 8;
#pragma unroll
        for (int j = 0; j < 10; j++) {
            int col = nh * 80 + j * 8 + tig * 2;
            if (mA < TT) {
                float2 v;
                v.x = acc[j][0];
                v.y = acc[j][1];
                *(float2*)(C + (size_t)mA * LDP + col) = v;
            }
            if (mB < TT) {
                float2 v;
                v.x = acc[j][2];
                v.y = acc[j][3];
                *(float2*)(C + (size_t)mB * LDP + col) = v;
            }
        }
    }
}

// Attention MLP tail
__global__ __launch_bounds__(512, 1) void attn_tail(
    const float* __restrict__ b1, const float* __restrict__ W2,
    const float* __restrict__ b2, const float* __restrict__ W3,
    const float* __restrict__ b3) {
    extern __shared__ __align__(16) float smf[];
    float* W2T = smf;
    float* W3s = W2T + 160 * 154;
    float* b2s = W3s + 160;
    float* h1s = b2s + 160;

    const int tid = threadIdx.x;
    for (int i = tid; i < 160 * 154; i += 512) W2T[i] = 0.f;
    if (tid < 160) {
        W3s[tid] = (tid < 150) ? W3[tid] : 0.f;
        b2s[tid] = (tid < 150) ? b2[tid] : 0.f;
    }
    __syncthreads();
    for (int i = tid; i < 22500; i += 512) {
        int k = i / 150;
        int j = i - k * 150;
        W2T[j * 154 + k] = W2[i];
    }

    const int t0 = blockIdx.x * 64;
    for (int idx = tid; idx < 64 * 150; idx += 512) {
        int t = idx / 150;
        int k = idx - t * 150;
        float v = 0.f;
        if (t0 + t < TT) v = fmaxf(g_Ha[(size_t)(t0 + t) * LDP + k] + b1[k], 0.f);
        h1s[t * 154 + k] = v;
    }
    __syncthreads();

    const int w = tid >> 5;
    const int lane = tid & 31;
    ull acc[4][5];
#pragma unroll
    for (int i = 0; i < 4; i++)
#pragma unroll
        for (int c = 0; c < 5; c++) acc[i][c] = 0ull;

#pragma unroll 5
    for (int kp = 0; kp < 75; kp++) {
        ull h2[4];
#pragma unroll
        for (int i = 0; i < 4; i++)
            h2[i] = *(const ull*)(h1s + (w * 4 + i) * 154 + 2 * kp);
#pragma unroll
        for (int c = 0; c < 5; c++) {
            ull b2v = *(const ull*)(W2T + (lane + 32 * c) * 154 + 2 * kp);
#pragma unroll
            for (int i = 0; i < 4; i++) fma2(acc[i][c], h2[i], b2v);
        }
    }
#pragma unroll
    for (int i = 0; i < 4; i++) {
        float p = 0.f;
#pragma unroll
        for (int c = 0; c < 5; c++) {
            int j = lane + 32 * c;
            if (j < 150) p += fmaxf(unpack_sum(acc[i][c]) + b2s[j], 0.f) * W3s[j];
        }
#pragma unroll
        for (int off = 16; off > 0; off >>= 1) p += __shfl_xor_sync(0xffffffffu, p, off);
        int t = w * 4 + i;
        if (lane == 0 && t0 + t < TT) g_logit[t0 + t] = p + b3[0];
    }
}

// Span scorer
__global__ __launch_bounds__(512, 1) void span_score(
    const float* __restrict__ b1, const float* __restrict__ W2,
    const float* __restrict__ b2, const float* __restrict__ W3,
    const float* __restrict__ b3, float* __restrict__ out, int totalTiles) {
    extern __shared__ __align__(16) float smf[];
    float* W2T = smf;
    float* W3s = W2T + 160 * 154;
    float* b2s = W3s + 160;
    float* b1s = b2s + 160;
    float* h1s = b1s + 160;
    float* PEs = h1s + 64 * 154;
    float* ws  = PEs + 73 * 150;

    const int tid = threadIdx.x;
    for (int i = tid; i < 160 * 154; i += 512) W2T[i] = 0.f;
    if (tid < 160) {
        W3s[tid] = (tid < 150) ? W3[tid] : 0.f;
        b2s[tid] = (tid < 150) ? b2[tid] : 0.f;
        b1s[tid] = (tid < 150) ? b1[tid] : 0.f;
    }
    __syncthreads();
    for (int i = tid; i < 22500; i += 512) {
        int k = i / 150;
        int j = i - k * 150;
        W2T[j * 154 + k] = W2[i];
    }
    const float bias3 = b3[0];
    const int w = tid >> 5;
    const int lane = tid & 31;

    for (int tile = blockIdx.x; tile < totalTiles; tile += gridDim.x) {
        int n = 1;
        int loc = tile;
#pragma unroll
        for (int nn = 1; nn <= 10; nn++) {
            int tn = (TT - nn + 1 + 63) >> 6;
            if (loc < tn) { n = nn; break; }
            loc -= tn;
        }
        const int s0 = loc << 6;
        const int S = TT - n + 1;
        const int cnt = min(64, S - s0);

        __syncthreads();

        const int rows = cnt + 9;
        for (int idx = tid; idx < rows * 150; idx += 512) {
            int r = idx / 150;
            int k = idx - r * 150;
            PEs[idx] = (s0 + r < TT) ? g_PE[(size_t)(s0 + r) * LDP + k] : 0.f;
        }
        if (tid < 64) {
            float l[10];
            if (tid < cnt) {
                int s = s0 + tid;
                float m = -1e30f;
                for (int j = 0; j < n; j++) { l[j] = g_logit[s + j]; m = fmaxf(m, l[j]); }
                float sum = 0.f;
                for (int j = 0; j < n; j++) { l[j] = expf(l[j] - m); sum += l[j]; }
                float inv = 1.f / sum;
#pragma unroll
                for (int j = 0; j < 10; j++) ws[tid * 10 + j] = (j < n) ? l[j] * inv : 0.f;
            } else {
#pragma unroll
                for (int j = 0; j < 10; j++) ws[tid * 10 + j] = 0.f;
            }
        }
        __syncthreads();

        for (int idx = tid; idx < 64 * 150; idx += 512) {
            int t = idx / 150;
            int k = idx - t * 150;
            float a = 0.f;
            if (t < cnt) {
                int s = s0 + t;
                a = g_Ps[(size_t)s * LDP + k] + g_Pe[(size_t)(s + n - 1) * LDP + k] + b1s[k];
#pragma unroll
                for (int j = 0; j < 10; j++)
                    a = fmaf(ws[t * 10 + j], PEs[(t + j) * 150 + k], a);
                a = fmaxf(a, 0.f);
            }
            h1s[t * 154 + k] = a;
        }
        __syncthreads();

        ull acc[4][5];
#pragma unroll
        for (int i = 0; i < 4; i++)
#pragma unroll
            for (int c = 0; c < 5; c++) acc[i][c] = 0ull;

#pragma unroll 5
        for (int kp = 0; kp < 75; kp++) {
            ull h2[4];
#pragma unroll
            for (int i = 0; i < 4; i++)
                h2[i] = *(const ull*)(h1s + (w * 4 + i) * 154 + 2 * kp);
#pragma unroll
            for (int c = 0; c < 5; c++) {
                ull b2v = *(const ull*)(W2T + (lane + 32 * c) * 154 + 2 * kp);
#pragma unroll
                for (int i = 0; i < 4; i++) fma2(acc[i][c], h2[i], b2v);
            }
        }
        const int base = (n - 1) * TT - ((n - 1) * (n - 2)) / 2;
#pragma unroll
        for (int i = 0; i < 4; i++) {
            float p = 0.f;
#pragma unroll
            for (int c = 0; c < 5; c++) {
                int j = lane + 32 * c;
                if (j < 150) p += fmaxf(unpack_sum(acc[i][c]) + b2s[j], 0.f) * W3s[j];
            }
#pragma unroll
            for (int off = 16; off > 0; off >>= 1) p += __shfl_xor_sync(0xffffffffu, p, off);
            int t = w * 4 + i;
            if (lane == 0 && t < cnt) out[base + s0 + t] = p + bias3;
        }
    }
}

extern "C" void kernel_launch(void* const* d_in, const int* in_sizes, int n_in,
                              void* d_out, int out_size) {
    const float* embeds = (const float*)d_in[0];
    const float* states = (const float*)d_in[1];
    const float* attn_W1 = (const float*)d_in[2];
    const float* attn_b1 = (const float*)d_in[3];
    const float* attn_W2 = (const float*)d_in[4];
    const float* attn_b2 = (const float*)d_in[5];
    const float* attn_W3 = (const float*)d_in[6];
    const float* attn_b3 = (const float*)d_in[7];
    const float* sc_W1 = (const float*)d_in[8];
    const float* sc_b1 = (const float*)d_in[9];
    const float* sc_W2 = (const float*)d_in[10];
    const float* sc_b2 = (const float*)d_in[11];
    const float* sc_W3 = (const float*)d_in[12];
    const float* sc_b3 = (const float*)d_in[13];
    float* out = (float*)d_out;

    float* pHa;
    float* pPs;
    float* pPe;
    float* pPE;
    cudaGetSymbolAddress((void**)&pHa, g_Ha);
    cudaGetSymbolAddress((void**)&pPs, g_Ps);
    cudaGetSymbolAddress((void**)&pPe, g_Pe);
    cudaGetSymbolAddress((void**)&pPE, g_PE);

    const int attnSmem = (160 * 154 + 160 + 160 + 64 * 154) * 4;
    const int spanSmem = (160 * 154 + 160 * 3 + 64 * 154 + 73 * 150 + 640) * 4;
    cudaFuncSetAttribute(proj_mma, cudaFuncAttributeMaxDynamicSharedMemorySize, PJ_SMEM);
    cudaFuncSetAttribute(attn_tail, cudaFuncAttributeMaxDynamicSharedMemorySize, attnSmem);
    cudaFuncSetAttribute(span_score, cudaFuncAttributeMaxDynamicSharedMemorySize, spanSmem);

    int totalTiles = 0;
    for (int nn = 1; nn <= 10; nn++) {
        totalTiles += (TT - nn + 1 + 63) >> 6;
    }

    proj_mma<<<313, 256, PJ_SMEM>>>(states, attn_W1, pHa, 400, 400);
    proj_mma<<<313, 256, PJ_SMEM>>>(states, sc_W1, pPs, 400, 400);
    proj_mma<<<313, 256, PJ_SMEM>>>(states, sc_W1 + 60000, pPe, 400, 400);
    proj_mma<<<313, 256, PJ_SMEM>>>(embeds, sc_W1 + 120000, pPE, 300, 300);
    attn_tail<<<313, 512, attnSmem>>>(attn_b1, attn_W2, attn_b2, attn_W3, attn_b3);
    span_score<<<148, 512, spanSmem>>>(sc_b1, sc_W2, sc_b2, sc_W3, sc_b3, out, totalTiles);
}

// round 13
// speedup vs baseline: 1.4323x; 1.1581x over previous
#include <cuda_runtime.h>

#define TT 20000
#define LDP 160

typedef unsigned long long ull;
typedef unsigned uns;
typedef unsigned short ush;

__device__ __forceinline__ void fma2(ull& d, ull a, ull b) {
    asm("fma.rn.f32x2 %0, %1, %2, %3;" : "=l"(d) : "l"(a), "l"(b), "l"(d));
}
__device__ __forceinline__ float unpack_sum(ull v) {
    return __uint_as_float((uns)v) + __uint_as_float((uns)(v >> 32));
}

// ---- scratch (static device globals; no allocation) ----
__device__ float g_Ha[(size_t)TT * LDP];
__device__ float g_Ps[(size_t)TT * LDP];
__device__ float g_Pe[(size_t)TT * LDP];
__device__ float g_PE[(size_t)TT * LDP];
__device__ float g_logit[TT];

// ---- bf16 mma.sync (base sm_80+ feature) ----
__device__ __forceinline__ void mma16816(float& c0, float& c1, float& c2, float& c3,
                                         uns a0, uns a1, uns a2, uns a3,
                                         uns b0, uns b1) {
    asm volatile("mma.sync.aligned.m16n8k16.row.col.f32.bf16.bf16.f32 {%0,%1,%2,%3}, {%4,%5,%6,%7}, {%8,%9}, {%0,%1,%2,%3};" : "+f"(c0), "+f"(c1), "+f"(c2), "+f"(c3) : "r"(a0), "r"(a1), "r"(a2), "r"(a3), "r"(b0), "r"(b1));
}

// ===================== proj_mma (unchanged from R12, passing) =====================
#define PJ_AH 0
#define PJ_AL 9216
#define PJ_BH 18432
#define PJ_BL 41472
#define PJ_SMEM 64512

__global__ __launch_bounds__(256, 2) void proj_mma(const float* __restrict__ A,
                                                   const float* __restrict__ B,
                                                   float* __restrict__ C,
                                                   int K, int lda) {
    extern __shared__ __align__(16) char smc[];
    const int tid = threadIdx.x;
    const int m0 = blockIdx.x * 64;
    const int warp = tid >> 5;
    const int lane = tid & 31;
    const int gid = lane >> 2;
    const int tig = lane & 3;
    const int mw = warp & 3;
    const int nh = warp >> 2;

    float acc[10][4];
#pragma unroll
    for (int j = 0; j < 10; j++) {
#pragma unroll
        for (int q = 0; q < 4; q++) acc[j][q] = 0.f;
    }

    const int nt = (K + 63) >> 6;
    for (int t = 0; t < nt; t++) {
        const int k0 = t << 6;
        __syncthreads();
        for (int idx = tid; idx < 2048; idx += 256) {
            int row = idx >> 5;
            int kp = idx & 31;
            int k = k0 + kp * 2;
            float2 v = make_float2(0.f, 0.f);
            if (m0 + row < TT && k < K)
                v = *(const float2*)(A + (size_t)(m0 + row) * lda + k);
            uns ux = __float_as_uint(v.x);
            uns uy = __float_as_uint(v.y);
            uns hx = ux & 0xFFFF0000u;
            uns hy = uy & 0xFFFF0000u;
            float rx = v.x - __uint_as_float(hx);
            float ry = v.y - __uint_as_float(hy);
            uns hip = (hx >> 16) | (hy & 0xFFFF0000u);
            uns lop = (__float_as_uint(rx) >> 16) | (__float_as_uint(ry) & 0xFFFF0000u);
            int boff = (row * 72 + kp * 2) * 2;
            *(uns*)(smc + PJ_AH + boff) = hip;
            *(uns*)(smc + PJ_AL + boff) = lop;
        }
        for (int idx = tid; idx < 10240; idx += 256) {
            int kk = idx / 160;
            int n = idx - kk * 160;
            float v = 0.f;
            if (n < 150 && k0 + kk < K) v = B[(k0 + kk) * 150 + n];
            uns u = __float_as_uint(v);
            uns h = u & 0xFFFF0000u;
            float r = v - __uint_as_float(h);
            int boff = (n * 72 + kk) * 2;
            *(ush*)(smc + PJ_BH + boff) = (ush)(h >> 16);
            *(ush*)(smc + PJ_BL + boff) = (ush)(__float_as_uint(r) >> 16);
        }
        __syncthreads();

#pragma unroll
        for (int ks = 0; ks < 4; ks++) {
            int arow0 = (mw * 16 + gid) * 72;
            int acol = ks * 16 + tig * 2;
            uns ah0 = *(uns*)(smc + PJ_AH + (arow0 + acol) * 2);
            uns ah1 = *(uns*)(smc + PJ_AH + (arow0 + 8 * 72 + acol) * 2);
            uns ah2 = *(uns*)(smc + PJ_AH + (arow0 + acol + 8) * 2);
            uns ah3 = *(uns*)(smc + PJ_AH + (arow0 + 8 * 72 + acol + 8) * 2);
            uns al0 = *(uns*)(smc + PJ_AL + (arow0 + acol) * 2);
            uns al1 = *(uns*)(smc + PJ_AL + (arow0 + 8 * 72 + acol) * 2);
            uns al2 = *(uns*)(smc + PJ_AL + (arow0 + acol + 8) * 2);
            uns al3 = *(uns*)(smc + PJ_AL + (arow0 + 8 * 72 + acol + 8) * 2);
#pragma unroll
            for (int j = 0; j < 10; j++) {
                int n = (nh * 10 + j) * 8 + gid;
                int kc = ks * 16 + tig * 2;
                uns bh0 = *(uns*)(smc + PJ_BH + (n * 72 + kc) * 2);
                uns bh1 = *(uns*)(smc + PJ_BH + (n * 72 + kc + 8) * 2);
                uns bl0 = *(uns*)(smc + PJ_BL + (n * 72 + kc) * 2);
                uns bl1 = *(uns*)(smc + PJ_BL + (n * 72 + kc + 8) * 2);
                mma16816(acc[j][0], acc[j][1], acc[j][2], acc[j][3], ah0, ah1, ah2, ah3, bh0, bh1);
                mma16816(acc[j][0], acc[j][1], acc[j][2], acc[j][3], ah0, ah1, ah2, ah3, bl0, bl1);
                mma16816(acc[j][0], acc[j][1], acc[j][2], acc[j][3], al0, al1, al2, al3, bh0, bh1);
            }
        }
    }

    {
        int mA = m0 + mw * 16 + gid;
        int mB = mA + 8;
#pragma unroll
        for (int j = 0; j < 10; j++) {
            int col = nh * 80 + j * 8 + tig * 2;
            if (mA < TT) {
                float2 v;
                v.x = acc[j][0];
                v.y = acc[j][1];
                *(float2*)(C + (size_t)mA * LDP + col) = v;
            }
            if (mB < TT) {
                float2 v;
                v.x = acc[j][2];
                v.y = acc[j][3];
                *(float2*)(C + (size_t)mB * LDP + col) = v;
            }
        }
    }
}

// ===================== attn_tail (unchanged, passing) =====================
__global__ __launch_bounds__(512, 1) void attn_tail(
    const float* __restrict__ b1, const float* __restrict__ W2,
    const float* __restrict__ b2, const float* __restrict__ W3,
    const float* __restrict__ b3) {
    extern __shared__ __align__(16) float smf[];
    float* W2T = smf;
    float* W3s = W2T + 160 * 154;
    float* b2s = W3s + 160;
    float* h1s = b2s + 160;

    const int tid = threadIdx.x;
    for (int i = tid; i < 160 * 154; i += 512) W2T[i] = 0.f;
    if (tid < 160) {
        W3s[tid] = (tid < 150) ? W3[tid] : 0.f;
        b2s[tid] = (tid < 150) ? b2[tid] : 0.f;
    }
    __syncthreads();
    for (int i = tid; i < 22500; i += 512) {
        int k = i / 150;
        int j = i - k * 150;
        W2T[j * 154 + k] = W2[i];
    }

    const int t0 = blockIdx.x * 64;
    for (int idx = tid; idx < 64 * 150; idx += 512) {
        int t = idx / 150;
        int k = idx - t * 150;
        float v = 0.f;
        if (t0 + t < TT) v = fmaxf(g_Ha[(size_t)(t0 + t) * LDP + k] + b1[k], 0.f);
        h1s[t * 154 + k] = v;
    }
    __syncthreads();

    const int w = tid >> 5;
    const int lane = tid & 31;
    ull acc[4][5];
#pragma unroll
    for (int i = 0; i < 4; i++)
#pragma unroll
        for (int c = 0; c < 5; c++) acc[i][c] = 0ull;

#pragma unroll 5
    for (int kp = 0; kp < 75; kp++) {
        ull h2[4];
#pragma unroll
        for (int i = 0; i < 4; i++)
            h2[i] = *(const ull*)(h1s + (w * 4 + i) * 154 + 2 * kp);
#pragma unroll
        for (int c = 0; c < 5; c++) {
            ull b2v = *(const ull*)(W2T + (lane + 32 * c) * 154 + 2 * kp);
#pragma unroll
            for (int i = 0; i < 4; i++) fma2(acc[i][c], h2[i], b2v);
        }
    }
#pragma unroll
    for (int i = 0; i < 4; i++) {
        float p = 0.f;
#pragma unroll
        for (int c = 0; c < 5; c++) {
            int j = lane + 32 * c;
            if (j < 150) p += fmaxf(unpack_sum(acc[i][c]) + b2s[j], 0.f) * W3s[j];
        }
#pragma unroll
        for (int off = 16; off > 0; off >>= 1) p += __shfl_xor_sync(0xffffffffu, p, off);
        int t = w * 4 + i;
        if (lane == 0 && t0 + t < TT) g_logit[t0 + t] = p + b3[0];
    }
}

// ===================== span_score with mma.sync layer-2 =====================
// smem byte offsets (stride 168 bf16 rows for mma operands)
#define SP_W2H 0
#define SP_W2L 53760
#define SP_H1H 107520
#define SP_H1L 129024
#define SP_PES 150528
#define SP_WS  194328
#define SP_B2  196888
#define SP_W3  197528
#define SP_B1  198168
#define SP_PRT 198808
#define SP_SMEM 199832

__global__ __launch_bounds__(512, 1) void span_score(
    const float* __restrict__ b1, const float* __restrict__ W2,
    const float* __restrict__ b2, const float* __restrict__ W3,
    const float* __restrict__ b3, float* __restrict__ out, int totalTiles) {
    extern __shared__ __align__(16) char smc[];
    float* PEs = (float*)(smc + SP_PES);
    float* ws  = (float*)(smc + SP_WS);
    float* b2s = (float*)(smc + SP_B2);
    float* W3s = (float*)(smc + SP_W3);
    float* b1s = (float*)(smc + SP_B1);
    float* prt = (float*)(smc + SP_PRT);

    const int tid = threadIdx.x;
    const int warp = tid >> 5;
    const int lane = tid & 31;
    const int gid = lane >> 2;
    const int tig = lane & 3;
    const int mw = warp & 3;       // m-tile 0..3
    const int nq = warp >> 2;      // n-quarter 0..3

    // ---- one-time staging: W2 bf16 hi/lo [n][k] stride 168, zero-padded ----
    for (int i = tid; i < 13440; i += 512) {
        *(uns*)(smc + SP_W2H + i * 4) = 0u;
        *(uns*)(smc + SP_W2L + i * 4) = 0u;
    }
    if (tid < 160) {
        W3s[tid] = (tid < 150) ? W3[tid] : 0.f;
        b2s[tid] = (tid < 150) ? b2[tid] : 0.f;
        b1s[tid] = (tid < 150) ? b1[tid] : 0.f;
    }
    // zero h1 k-pad columns (k=150..167) once; rows rewritten each tile
    for (int i = tid; i < 64 * 18; i += 512) {
        int t = i / 18;
        int k = 150 + i - (i / 18) * 18;
        *(ush*)(smc + SP_H1H + (t * 168 + k) * 2) = 0;
        *(ush*)(smc + SP_H1L + (t * 168 + k) * 2) = 0;
    }
    __syncthreads();
    for (int i = tid; i < 22500; i += 512) {
        int k = i / 150;
        int j = i - k * 150;
        float v = W2[i];
        uns u = __float_as_uint(v);
        uns h = u & 0xFFFF0000u;
        float r = v - __uint_as_float(h);
        int boff = (j * 168 + k) * 2;
        *(ush*)(smc + SP_W2H + boff) = (ush)(h >> 16);
        *(ush*)(smc + SP_W2L + boff) = (ush)(__float_as_uint(r) >> 16);
    }
    const float bias3 = b3[0];

    for (int tile = blockIdx.x; tile < totalTiles; tile += gridDim.x) {
        int n = 1;
        int loc = tile;
#pragma unroll
        for (int nn = 1; nn <= 10; nn++) {
            int tn = (TT - nn + 1 + 63) >> 6;
            if (loc < tn) { n = nn; break; }
            loc -= tn;
        }
        const int s0 = loc << 6;
        const int S = TT - n + 1;
        const int cnt = min(64, S - s0);

        __syncthreads();   // previous tile's readers done

        const int rows = cnt + 9;
        for (int idx = tid; idx < rows * 150; idx += 512) {
            int r = idx / 150;
            int k = idx - r * 150;
            PEs[idx] = (s0 + r < TT) ? g_PE[(size_t)(s0 + r) * LDP + k] : 0.f;
        }
        if (tid < 64) {
            float l[10];
            if (tid < cnt) {
                int s = s0 + tid;
                float m = -1e30f;
                for (int j = 0; j < n; j++) { l[j] = g_logit[s + j]; m = fmaxf(m, l[j]); }
                float sum = 0.f;
                for (int j = 0; j < n; j++) { l[j] = expf(l[j] - m); sum += l[j]; }
                float inv = 1.f / sum;
#pragma unroll
                for (int j = 0; j < 10; j++) ws[tid * 10 + j] = (j < n) ? l[j] * inv : 0.f;
            } else {
#pragma unroll
                for (int j = 0; j < 10; j++) ws[tid * 10 + j] = 0.f;
            }
        }
        __syncthreads();

        // h1 = relu(Ps + Pe + b1 + pooled PE)  -> bf16 hi/lo smem, stride 168
        for (int idx = tid; idx < 64 * 150; idx += 512) {
            int t = idx / 150;
            int k = idx - t * 150;
            float a = 0.f;
            if (t < cnt) {
                int s = s0 + t;
                a = g_Ps[(size_t)s * LDP + k] + g_Pe[(size_t)(s + n - 1) * LDP + k] + b1s[k];
#pragma unroll
                for (int j = 0; j < 10; j++)
                    a = fmaf(ws[t * 10 + j], PEs[(t + j) * 150 + k], a);
                a = fmaxf(a, 0.f);
            }
            uns u = __float_as_uint(a);
            uns h = u & 0xFFFF0000u;
            float r = a - __uint_as_float(h);
            int boff = (t * 168 + k) * 2;
            *(ush*)(smc + SP_H1H + boff) = (ush)(h >> 16);
            *(ush*)(smc + SP_H1L + boff) = (ush)(__float_as_uint(r) >> 16);
        }
        __syncthreads();

        // layer 2: mma.sync, warp = (m-tile mw, n-quarter nq), 5 n8-tiles, K=160
        float acc[5][4];
#pragma unroll
        for (int j = 0; j < 5; j++) {
#pragma unroll
            for (int q = 0; q < 4; q++) acc[j][q] = 0.f;
        }
#pragma unroll
        for (int ks = 0; ks < 10; ks++) {
            int arow0 = (mw * 16 + gid) * 168;
            int acol = ks * 16 + tig * 2;
            uns ah0 = *(uns*)(smc + SP_H1H + (arow0 + acol) * 2);
            uns ah1 = *(uns*)(smc + SP_H1H + (arow0 + 8 * 168 + acol) * 2);
            uns ah2 = *(uns*)(smc + SP_H1H + (arow0 + acol + 8) * 2);
            uns ah3 = *(uns*)(smc + SP_H1H + (arow0 + 8 * 168 + acol + 8) * 2);
            uns al0 = *(uns*)(smc + SP_H1L + (arow0 + acol) * 2);
            uns al1 = *(uns*)(smc + SP_H1L + (arow0 + 8 * 168 + acol) * 2);
            uns al2 = *(uns*)(smc + SP_H1L + (arow0 + acol + 8) * 2);
            uns al3 = *(uns*)(smc + SP_H1L + (arow0 + 8 * 168 + acol + 8) * 2);
#pragma unroll
            for (int j = 0; j < 5; j++) {
                int nn = (nq * 5 + j) * 8 + gid;
                int kc = ks * 16 + tig * 2;
                uns bh0 = *(uns*)(smc + SP_W2H + (nn * 168 + kc) * 2);
                uns bh1 = *(uns*)(smc + SP_W2H + (nn * 168 + kc + 8) * 2);
                uns bl0 = *(uns*)(smc + SP_W2L + (nn * 168 + kc) * 2);
                uns bl1 = *(uns*)(smc + SP_W2L + (nn * 168 + kc + 8) * 2);
                mma16816(acc[j][0], acc[j][1], acc[j][2], acc[j][3], ah0, ah1, ah2, ah3, bh0, bh1);
                mma16816(acc[j][0], acc[j][1], acc[j][2], acc[j][3], ah0, ah1, ah2, ah3, bl0, bl1);
                mma16816(acc[j][0], acc[j][1], acc[j][2], acc[j][3], al0, al1, al2, al3, bh0, bh1);
            }
        }

        // layer 3: relu(acc + b2) . W3, quad-reduce, cross-warp via smem
        float pA = 0.f;
        float pB = 0.f;
#pragma unroll
        for (int j = 0; j < 5; j++) {
            int col = (nq * 5 + j) * 8 + tig * 2;
#pragma unroll
            for (int c = 0; c < 2; c++) {
                float w3v = W3s[col + c];
                float b2v = b2s[col + c];
                pA += fmaxf(acc[j][c] + b2v, 0.f) * w3v;
                pB += fmaxf(acc[j][2 + c] + b2v, 0.f) * w3v;
            }
        }
        pA += __shfl_xor_sync(0xffffffffu, pA, 1);
        pA += __shfl_xor_sync(0xffffffffu, pA, 2);
        pB += __shfl_xor_sync(0xffffffffu, pB, 1);
        pB += __shfl_xor_sync(0xffffffffu, pB, 2);
        if (tig == 0) {
            prt[(mw * 16 + gid) * 4 + nq] = pA;
            prt[(mw * 16 + gid + 8) * 4 + nq] = pB;
        }
        __syncthreads();

        if (tid < 64 && tid < cnt) {
            const int base = (n - 1) * TT - ((n - 1) * (n - 2)) / 2;
            float sum = prt[tid * 4] + prt[tid * 4 + 1] + prt[tid * 4 + 2] + prt[tid * 4 + 3];
            out[base + s0 + tid] = sum + bias3;
        }
    }
}

extern "C" void kernel_launch(void* const* d_in, const int* in_sizes, int n_in,
                              void* d_out, int out_size) {
    const float* embeds = (const float*)d_in[0];
    const float* states = (const float*)d_in[1];
    const float* attn_W1 = (const float*)d_in[2];
    const float* attn_b1 = (const float*)d_in[3];
    const float* attn_W2 = (const float*)d_in[4];
    const float* attn_b2 = (const float*)d_in[5];
    const float* attn_W3 = (const float*)d_in[6];
    const float* attn_b3 = (const float*)d_in[7];
    const float* sc_W1 = (const float*)d_in[8];
    const float* sc_b1 = (const float*)d_in[9];
    const float* sc_W2 = (const float*)d_in[10];
    const float* sc_b2 = (const float*)d_in[11];
    const float* sc_W3 = (const float*)d_in[12];
    const float* sc_b3 = (const float*)d_in[13];
    float* out = (float*)d_out;

    float* pHa;
    float* pPs;
    float* pPe;
    float* pPE;
    cudaGetSymbolAddress((void**)&pHa, g_Ha);
    cudaGetSymbolAddress((void**)&pPs, g_Ps);
    cudaGetSymbolAddress((void**)&pPe, g_Pe);
    cudaGetSymbolAddress((void**)&pPE, g_PE);

    const int attnSmem = (160 * 154 + 160 + 160 + 64 * 154) * 4;
    cudaFuncSetAttribute(proj_mma, cudaFuncAttributeMaxDynamicSharedMemorySize, PJ_SMEM);
    cudaFuncSetAttribute(attn_tail, cudaFuncAttributeMaxDynamicSharedMemorySize, attnSmem);
    cudaFuncSetAttribute(span_score, cudaFuncAttributeMaxDynamicSharedMemorySize, SP_SMEM);

    int totalTiles = 0;
    for (int nn = 1; nn <= 10; nn++) {
        totalTiles += (TT - nn + 1 + 63) >> 6;
    }

    proj_mma<<<313, 256, PJ_SMEM>>>(states, attn_W1, pHa, 400, 400);
    proj_mma<<<313, 256, PJ_SMEM>>>(states, sc_W1, pPs, 400, 400);
    proj_mma<<<313, 256, PJ_SMEM>>>(states, sc_W1 + 60000, pPe, 400, 400);
    proj_mma<<<313, 256, PJ_SMEM>>>(embeds, sc_W1 + 120000, pPE, 300, 300);
    attn_tail<<<313, 512, attnSmem>>>(attn_b1, attn_W2, attn_b2, attn_W3, attn_b3);
    span_score<<<148, 512, SP_SMEM>>>(sc_b1, sc_W2, sc_b2, sc_W3, sc_b3, out, totalTiles);
}

// round 14
// speedup vs baseline: 1.9733x; 1.3777x over previous
#include <cuda_runtime.h>

#define TT 20000
#define LDP 160

typedef unsigned long long ull;
typedef unsigned uns;
typedef unsigned short ush;

__device__ __forceinline__ void fma2(ull& d, ull a, ull b) {
    asm("fma.rn.f32x2 %0, %1, %2, %3;" : "=l"(d) : "l"(a), "l"(b), "l"(d));
}
__device__ __forceinline__ float unpack_sum(ull v) {
    return __uint_as_float((uns)v) + __uint_as_float((uns)(v >> 32));
}

// ---- scratch (static device globals; no allocation) ----
__device__ float g_Ha[(size_t)TT * LDP];
__device__ float g_Ps[(size_t)TT * LDP];
__device__ float g_Pe[(size_t)TT * LDP];
__device__ float g_PE[(size_t)TT * LDP];
__device__ float g_logit[TT];

// ---- bf16 mma.sync (base sm_80+ feature) ----
__device__ __forceinline__ void mma16816(float& c0, float& c1, float& c2, float& c3,
                                         uns a0, uns a1, uns a2, uns a3,
                                         uns b0, uns b1) {
    asm volatile("mma.sync.aligned.m16n8k16.row.col.f32.bf16.bf16.f32 {%0,%1,%2,%3}, {%4,%5,%6,%7}, {%8,%9}, {%0,%1,%2,%3};" : "+f"(c0), "+f"(c1), "+f"(c2), "+f"(c3) : "r"(a0), "r"(a1), "r"(a2), "r"(a3), "r"(b0), "r"(b1));
}

// ===================== fused proj_mma: 128-row tiles, 512 thr, 4 jobs =====================
#define PJ_AH 0
#define PJ_AL 18432
#define PJ_BH 36864
#define PJ_BL 59904
#define PJ_SMEM 82944

__global__ __launch_bounds__(512, 1) void proj_mma(
    const float* __restrict__ A0, const float* __restrict__ B0, float* __restrict__ C0,
    const float* __restrict__ A1, const float* __restrict__ B1, float* __restrict__ C1,
    const float* __restrict__ A2, const float* __restrict__ B2, float* __restrict__ C2,
    const float* __restrict__ A3, const float* __restrict__ B3, float* __restrict__ C3) {
    extern __shared__ __align__(16) char smc[];
    const float* __restrict__ A;
    const float* __restrict__ B;
    float* __restrict__ C;
    int K;
    const int jid = blockIdx.y;
    if (jid == 0) { A = A0; B = B0; C = C0; K = 400; }
    else if (jid == 1) { A = A1; B = B1; C = C1; K = 400; }
    else if (jid == 2) { A = A2; B = B2; C = C2; K = 400; }
    else { A = A3; B = B3; C = C3; K = 300; }
    const int lda = K;

    const int tid = threadIdx.x;
    const int m0 = blockIdx.x * 128;
    const int warp = tid >> 5;
    const int lane = tid & 31;
    const int gid = lane >> 2;
    const int tig = lane & 3;
    const int mw = warp >> 1;       // m-tile 0..7
    const int nh = warp & 1;        // n-half 0..1

    float acc[10][4];
#pragma unroll
    for (int j = 0; j < 10; j++) {
#pragma unroll
        for (int q = 0; q < 4; q++) acc[j][q] = 0.f;
    }

    const int nt = (K + 63) >> 6;
    for (int t = 0; t < nt; t++) {
        const int k0 = t << 6;
        __syncthreads();
        // stage A: 128 rows x 32 k-pairs
        for (int idx = tid; idx < 4096; idx += 512) {
            int row = idx >> 5;
            int kp = idx & 31;
            int k = k0 + kp * 2;
            float2 v = make_float2(0.f, 0.f);
            if (m0 + row < TT && k < K)
                v = *(const float2*)(A + (size_t)(m0 + row) * lda + k);
            uns ux = __float_as_uint(v.x);
            uns uy = __float_as_uint(v.y);
            uns hx = ux & 0xFFFF0000u;
            uns hy = uy & 0xFFFF0000u;
            float rx = v.x - __uint_as_float(hx);
            float ry = v.y - __uint_as_float(hy);
            uns hip = (hx >> 16) | (hy & 0xFFFF0000u);
            uns lop = (__float_as_uint(rx) >> 16) | (__float_as_uint(ry) & 0xFFFF0000u);
            int boff = (row * 72 + kp * 2) * 2;
            *(uns*)(smc + PJ_AH + boff) = hip;
            *(uns*)(smc + PJ_AL + boff) = lop;
        }
        // stage B transposed [n][k]
        for (int idx = tid; idx < 10240; idx += 512) {
            int kk = idx / 160;
            int n = idx - kk * 160;
            float v = 0.f;
            if (n < 150 && k0 + kk < K) v = B[(k0 + kk) * 150 + n];
            uns u = __float_as_uint(v);
            uns h = u & 0xFFFF0000u;
            float r = v - __uint_as_float(h);
            int boff = (n * 72 + kk) * 2;
            *(ush*)(smc + PJ_BH + boff) = (ush)(h >> 16);
            *(ush*)(smc + PJ_BL + boff) = (ush)(__float_as_uint(r) >> 16);
        }
        __syncthreads();

#pragma unroll
        for (int ks = 0; ks < 4; ks++) {
            int arow0 = (mw * 16 + gid) * 72;
            int acol = ks * 16 + tig * 2;
            uns ah0 = *(uns*)(smc + PJ_AH + (arow0 + acol) * 2);
            uns ah1 = *(uns*)(smc + PJ_AH + (arow0 + 8 * 72 + acol) * 2);
            uns ah2 = *(uns*)(smc + PJ_AH + (arow0 + acol + 8) * 2);
            uns ah3 = *(uns*)(smc + PJ_AH + (arow0 + 8 * 72 + acol + 8) * 2);
            uns al0 = *(uns*)(smc + PJ_AL + (arow0 + acol) * 2);
            uns al1 = *(uns*)(smc + PJ_AL + (arow0 + 8 * 72 + acol) * 2);
            uns al2 = *(uns*)(smc + PJ_AL + (arow0 + acol + 8) * 2);
            uns al3 = *(uns*)(smc + PJ_AL + (arow0 + 8 * 72 + acol + 8) * 2);
#pragma unroll
            for (int j = 0; j < 10; j++) {
                int n = (nh * 10 + j) * 8 + gid;
                int kc = ks * 16 + tig * 2;
                uns bh0 = *(uns*)(smc + PJ_BH + (n * 72 + kc) * 2);
                uns bh1 = *(uns*)(smc + PJ_BH + (n * 72 + kc + 8) * 2);
                uns bl0 = *(uns*)(smc + PJ_BL + (n * 72 + kc) * 2);
                uns bl1 = *(uns*)(smc + PJ_BL + (n * 72 + kc + 8) * 2);
                mma16816(acc[j][0], acc[j][1], acc[j][2], acc[j][3], ah0, ah1, ah2, ah3, bh0, bh1);
                mma16816(acc[j][0], acc[j][1], acc[j][2], acc[j][3], ah0, ah1, ah2, ah3, bl0, bl1);
                mma16816(acc[j][0], acc[j][1], acc[j][2], acc[j][3], al0, al1, al2, al3, bh0, bh1);
            }
        }
    }

    {
        int mA = m0 + mw * 16 + gid;
        int mB = mA + 8;
#pragma unroll
        for (int j = 0; j < 10; j++) {
            int col = nh * 80 + j * 8 + tig * 2;
            if (mA < TT) {
                float2 v;
                v.x = acc[j][0];
                v.y = acc[j][1];
                *(float2*)(C + (size_t)mA * LDP + col) = v;
            }
            if (mB < TT) {
                float2 v;
                v.x = acc[j][2];
                v.y = acc[j][3];
                *(float2*)(C + (size_t)mB * LDP + col) = v;
            }
        }
    }
}

// ===================== attn_tail (unchanged, passing) =====================
__global__ __launch_bounds__(512, 1) void attn_tail(
    const float* __restrict__ b1, const float* __restrict__ W2,
    const float* __restrict__ b2, const float* __restrict__ W3,
    const float* __restrict__ b3) {
    extern __shared__ __align__(16) float smf[];
    float* W2T = smf;
    float* W3s = W2T + 160 * 154;
    float* b2s = W3s + 160;
    float* h1s = b2s + 160;

    const int tid = threadIdx.x;
    for (int i = tid; i < 160 * 154; i += 512) W2T[i] = 0.f;
    if (tid < 160) {
        W3s[tid] = (tid < 150) ? W3[tid] : 0.f;
        b2s[tid] = (tid < 150) ? b2[tid] : 0.f;
    }
    __syncthreads();
    for (int i = tid; i < 22500; i += 512) {
        int k = i / 150;
        int j = i - k * 150;
        W2T[j * 154 + k] = W2[i];
    }

    const int t0 = blockIdx.x * 64;
    for (int idx = tid; idx < 64 * 150; idx += 512) {
        int t = idx / 150;
        int k = idx - t * 150;
        float v = 0.f;
        if (t0 + t < TT) v = fmaxf(g_Ha[(size_t)(t0 + t) * LDP + k] + b1[k], 0.f);
        h1s[t * 154 + k] = v;
    }
    __syncthreads();

    const int w = tid >> 5;
    const int lane = tid & 31;
    ull acc[4][5];
#pragma unroll
    for (int i = 0; i < 4; i++)
#pragma unroll
        for (int c = 0; c < 5; c++) acc[i][c] = 0ull;

#pragma unroll 5
    for (int kp = 0; kp < 75; kp++) {
        ull h2[4];
#pragma unroll
        for (int i = 0; i < 4; i++)
            h2[i] = *(const ull*)(h1s + (w * 4 + i) * 154 + 2 * kp);
#pragma unroll
        for (int c = 0; c < 5; c++) {
            ull b2v = *(const ull*)(W2T + (lane + 32 * c) * 154 + 2 * kp);
#pragma unroll
            for (int i = 0; i < 4; i++) fma2(acc[i][c], h2[i], b2v);
        }
    }
#pragma unroll
    for (int i = 0; i < 4; i++) {
        float p = 0.f;
#pragma unroll
        for (int c = 0; c < 5; c++) {
            int j = lane + 32 * c;
            if (j < 150) p += fmaxf(unpack_sum(acc[i][c]) + b2s[j], 0.f) * W3s[j];
        }
#pragma unroll
        for (int off = 16; off > 0; off >>= 1) p += __shfl_xor_sync(0xffffffffu, p, off);
        int t = w * 4 + i;
        if (lane == 0 && t0 + t < TT) g_logit[t0 + t] = p + b3[0];
    }
}

// ===================== span_score (mma layer-2, vectorized pooling) =====================
#define SP_W2H 0
#define SP_W2L 53760
#define SP_H1H 107520
#define SP_H1L 129024
#define SP_PES 150528
#define SP_WS  194328
#define SP_B2  196888
#define SP_W3  197528
#define SP_B1  198168
#define SP_PRT 198808
#define SP_SMEM 199832

__global__ __launch_bounds__(512, 1) void span_score(
    const float* __restrict__ b1, const float* __restrict__ W2,
    const float* __restrict__ b2, const float* __restrict__ W3,
    const float* __restrict__ b3, float* __restrict__ out, int totalTiles) {
    extern __shared__ __align__(16) char smc[];
    float* PEs = (float*)(smc + SP_PES);
    float* ws  = (float*)(smc + SP_WS);
    float* b2s = (float*)(smc + SP_B2);
    float* W3s = (float*)(smc + SP_W3);
    float* b1s = (float*)(smc + SP_B1);
    float* prt = (float*)(smc + SP_PRT);

    const int tid = threadIdx.x;
    const int warp = tid >> 5;
    const int lane = tid & 31;
    const int gid = lane >> 2;
    const int tig = lane & 3;
    const int mw = warp & 3;
    const int nq = warp >> 2;

    for (int i = tid; i < 13440; i += 512) {
        *(uns*)(smc + SP_W2H + i * 4) = 0u;
        *(uns*)(smc + SP_W2L + i * 4) = 0u;
    }
    if (tid < 160) {
        W3s[tid] = (tid < 150) ? W3[tid] : 0.f;
        b2s[tid] = (tid < 150) ? b2[tid] : 0.f;
        b1s[tid] = (tid < 150) ? b1[tid] : 0.f;
    }
    for (int i = tid; i < 64 * 18; i += 512) {
        int t = i / 18;
        int k = 150 + i - (i / 18) * 18;
        *(ush*)(smc + SP_H1H + (t * 168 + k) * 2) = 0;
        *(ush*)(smc + SP_H1L + (t * 168 + k) * 2) = 0;
    }
    __syncthreads();
    for (int i = tid; i < 22500; i += 512) {
        int k = i / 150;
        int j = i - k * 150;
        float v = W2[i];
        uns u = __float_as_uint(v);
        uns h = u & 0xFFFF0000u;
        float r = v - __uint_as_float(h);
        int boff = (j * 168 + k) * 2;
        *(ush*)(smc + SP_W2H + boff) = (ush)(h >> 16);
        *(ush*)(smc + SP_W2L + boff) = (ush)(__float_as_uint(r) >> 16);
    }
    const float bias3 = b3[0];
    const int myrow = tid >> 3;          // 0..63 (h1-build row)
    const int klane = (tid & 7) * 2;     // even col base

    for (int tile = blockIdx.x; tile < totalTiles; tile += gridDim.x) {
        int n = 1;
        int loc = tile;
#pragma unroll
        for (int nn = 1; nn <= 10; nn++) {
            int tn = (TT - nn + 1 + 63) >> 6;
            if (loc < tn) { n = nn; break; }
            loc -= tn;
        }
        const int s0 = loc << 6;
        const int S = TT - n + 1;
        const int cnt = min(64, S - s0);

        __syncthreads();

        // stage PE rows as float2 (always 73 rows; OOB -> 0)
        for (int idx = tid; idx < 73 * 75; idx += 512) {
            int r = idx / 75;
            int k2 = idx - r * 75;
            float2 v = make_float2(0.f, 0.f);
            if (s0 + r < TT) v = *(const float2*)(g_PE + (size_t)(s0 + r) * LDP + k2 * 2);
            *(float2*)(PEs + r * 150 + k2 * 2) = v;
        }
        if (tid < 64) {
            float l[10];
            if (tid < cnt) {
                int s = s0 + tid;
                float m = -1e30f;
                for (int j = 0; j < n; j++) { l[j] = g_logit[s + j]; m = fmaxf(m, l[j]); }
                float sum = 0.f;
                for (int j = 0; j < n; j++) { l[j] = expf(l[j] - m); sum += l[j]; }
                float inv = 1.f / sum;
#pragma unroll
                for (int j = 0; j < 10; j++) ws[tid * 10 + j] = (j < n) ? l[j] * inv : 0.f;
            } else {
#pragma unroll
                for (int j = 0; j < 10; j++) ws[tid * 10 + j] = 0.f;
            }
        }
        __syncthreads();

        // h1 build: 8 threads per row, weights in registers, float2 columns
        {
            const int t = myrow;
            const bool valid = t < cnt;
            const int s = s0 + t;
            float wr[10];
#pragma unroll
            for (int j = 0; j < 10; j++) wr[j] = ws[t * 10 + j];
            const float* psrow = g_Ps + (size_t)s * LDP;
            const float* perow = g_Pe + (size_t)(s + n - 1) * LDP;
#pragma unroll
            for (int i = 0; i < 10; i++) {
                int k = klane + 16 * i;
                if (k < 150) {
                    float ax = 0.f;
                    float ay = 0.f;
                    if (valid) {
                        float2 p1 = *(const float2*)(psrow + k);
                        float2 p2 = *(const float2*)(perow + k);
                        float2 bb = *(const float2*)(b1s + k);
                        ax = p1.x + p2.x + bb.x;
                        ay = p1.y + p2.y + bb.y;
#pragma unroll
                        for (int j = 0; j < 10; j++) {
                            float2 pe = *(const float2*)(PEs + (t + j) * 150 + k);
                            ax = fmaf(wr[j], pe.x, ax);
                            ay = fmaf(wr[j], pe.y, ay);
                        }
                        ax = fmaxf(ax, 0.f);
                        ay = fmaxf(ay, 0.f);
                    }
                    uns ux = __float_as_uint(ax);
                    uns uy = __float_as_uint(ay);
                    uns hx = ux & 0xFFFF0000u;
                    uns hy = uy & 0xFFFF0000u;
                    float rx = ax - __uint_as_float(hx);
                    float ry = ay - __uint_as_float(hy);
                    uns hip = (hx >> 16) | (hy & 0xFFFF0000u);
                    uns lop = (__float_as_uint(rx) >> 16) | (__float_as_uint(ry) & 0xFFFF0000u);
                    int boff = (t * 168 + k) * 2;
                    *(uns*)(smc + SP_H1H + boff) = hip;
                    *(uns*)(smc + SP_H1L + boff) = lop;
                }
            }
        }
        __syncthreads();

        float acc[5][4];
#pragma unroll
        for (int j = 0; j < 5; j++) {
#pragma unroll
            for (int q = 0; q < 4; q++) acc[j][q] = 0.f;
        }
#pragma unroll
        for (int ks = 0; ks < 10; ks++) {
            int arow0 = (mw * 16 + gid) * 168;
            int acol = ks * 16 + tig * 2;
            uns ah0 = *(uns*)(smc + SP_H1H + (arow0 + acol) * 2);
            uns ah1 = *(uns*)(smc + SP_H1H + (arow0 + 8 * 168 + acol) * 2);
            uns ah2 = *(uns*)(smc + SP_H1H + (arow0 + acol + 8) * 2);
            uns ah3 = *(uns*)(smc + SP_H1H + (arow0 + 8 * 168 + acol + 8) * 2);
            uns al0 = *(uns*)(smc + SP_H1L + (arow0 + acol) * 2);
            uns al1 = *(uns*)(smc + SP_H1L + (arow0 + 8 * 168 + acol) * 2);
            uns al2 = *(uns*)(smc + SP_H1L + (arow0 + acol + 8) * 2);
            uns al3 = *(uns*)(smc + SP_H1L + (arow0 + 8 * 168 + acol + 8) * 2);
#pragma unroll
            for (int j = 0; j < 5; j++) {
                int nn = (nq * 5 + j) * 8 + gid;
                int kc = ks * 16 + tig * 2;
                uns bh0 = *(uns*)(smc + SP_W2H + (nn * 168 + kc) * 2);
                uns bh1 = *(uns*)(smc + SP_W2H + (nn * 168 + kc + 8) * 2);
                uns bl0 = *(uns*)(smc + SP_W2L + (nn * 168 + kc) * 2);
                uns bl1 = *(uns*)(smc + SP_W2L + (nn * 168 + kc + 8) * 2);
                mma16816(acc[j][0], acc[j][1], acc[j][2], acc[j][3], ah0, ah1, ah2, ah3, bh0, bh1);
                mma16816(acc[j][0], acc[j][1], acc[j][2], acc[j][3], ah0, ah1, ah2, ah3, bl0, bl1);
                mma16816(acc[j][0], acc[j][1], acc[j][2], acc[j][3], al0, al1, al2, al3, bh0, bh1);
            }
        }

        float pA = 0.f;
        float pB = 0.f;
#pragma unroll
        for (int j = 0; j < 5; j++) {
            int col = (nq * 5 + j) * 8 + tig * 2;
#pragma unroll
            for (int c = 0; c < 2; c++) {
                float w3v = W3s[col + c];
                float b2v = b2s[col + c];
                pA += fmaxf(acc[j][c] + b2v, 0.f) * w3v;
                pB += fmaxf(acc[j][2 + c] + b2v, 0.f) * w3v;
            }
        }
        pA += __shfl_xor_sync(0xffffffffu, pA, 1);
        pA += __shfl_xor_sync(0xffffffffu, pA, 2);
        pB += __shfl_xor_sync(0xffffffffu, pB, 1);
        pB += __shfl_xor_sync(0xffffffffu, pB, 2);
        if (tig == 0) {
            prt[(mw * 16 + gid) * 4 + nq] = pA;
            prt[(mw * 16 + gid + 8) * 4 + nq] = pB;
        }
        __syncthreads();

        if (tid < 64 && tid < cnt) {
            const int base = (n - 1) * TT - ((n - 1) * (n - 2)) / 2;
            float sum = prt[tid * 4] + prt[tid * 4 + 1] + prt[tid * 4 + 2] + prt[tid * 4 + 3];
            out[base + s0 + tid] = sum + bias3;
        }
    }
}

extern "C" void kernel_launch(void* const* d_in, const int* in_sizes, int n_in,
                              void* d_out, int out_size) {
    const float* embeds = (const float*)d_in[0];
    const float* states = (const float*)d_in[1];
    const float* attn_W1 = (const float*)d_in[2];
    const float* attn_b1 = (const float*)d_in[3];
    const float* attn_W2 = (const float*)d_in[4];
    const float* attn_b2 = (const float*)d_in[5];
    const float* attn_W3 = (const float*)d_in[6];
    const float* attn_b3 = (const float*)d_in[7];
    const float* sc_W1 = (const float*)d_in[8];
    const float* sc_b1 = (const float*)d_in[9];
    const float* sc_W2 = (const float*)d_in[10];
    const float* sc_b2 = (const float*)d_in[11];
    const float* sc_W3 = (const float*)d_in[12];
    const float* sc_b3 = (const float*)d_in[13];
    float* out = (float*)d_out;

    float* pHa;
    float* pPs;
    float* pPe;
    float* pPE;
    cudaGetSymbolAddress((void**)&pHa, g_Ha);
    cudaGetSymbolAddress((void**)&pPs, g_Ps);
    cudaGetSymbolAddress((void**)&pPe, g_Pe);
    cudaGetSymbolAddress((void**)&pPE, g_PE);

    const int attnSmem = (160 * 154 + 160 + 160 + 64 * 154) * 4;
    cudaFuncSetAttribute(proj_mma, cudaFuncAttributeMaxDynamicSharedMemorySize, PJ_SMEM);
    cudaFuncSetAttribute(attn_tail, cudaFuncAttributeMaxDynamicSharedMemorySize, attnSmem);
    cudaFuncSetAttribute(span_score, cudaFuncAttributeMaxDynamicSharedMemorySize, SP_SMEM);

    int totalTiles = 0;
    for (int nn = 1; nn <= 10; nn++) {
        totalTiles += (TT - nn + 1 + 63) >> 6;
    }

    dim3 projGrid(157, 4);
    proj_mma<<<projGrid, 512, PJ_SMEM>>>(
        states, attn_W1, pHa,
        states, sc_W1, pPs,
        states, sc_W1 + 60000, pPe,
        embeds, sc_W1 + 120000, pPE);
    attn_tail<<<313, 512, attnSmem>>>(attn_b1, attn_W2, attn_b2, attn_W3, attn_b3);
    span_score<<<148, 512, SP_SMEM>>>(sc_b1, sc_W2, sc_b2, sc_W3, sc_b3, out, totalTiles);
}

// round 17
// speedup vs baseline: 2.1052x; 1.0669x over previous
#include <cuda_runtime.h>

#define TT 20000
#define LDP 160

typedef unsigned long long ull;
typedef unsigned uns;
typedef unsigned short ush;

__device__ __forceinline__ void fma2(ull& d, ull a, ull b) {
    asm("fma.rn.f32x2 %0, %1, %2, %3;" : "=l"(d) : "l"(a), "l"(b), "l"(d));
}
__device__ __forceinline__ float unpack_sum(ull v) {
    return __uint_as_float((uns)v) + __uint_as_float((uns)(v >> 32));
}

// ---- scratch (static device globals; no allocation) ----
__device__ float g_Ha[(size_t)TT * LDP];
__device__ float g_Ps[(size_t)TT * LDP];
__device__ float g_Pe[(size_t)TT * LDP];
__device__ float g_PE[(size_t)TT * LDP];
__device__ float g_logit[TT];
// pre-split bf16 hi/lo buffers, k-stride 448 (zero padded)
__device__ ush g_sAH[(size_t)TT * 448];
__device__ ush g_sAL[(size_t)TT * 448];
__device__ ush g_eAH[(size_t)TT * 448];
__device__ ush g_eAL[(size_t)TT * 448];
__device__ ush g_WH[4 * 160 * 448];
__device__ ush g_WL[4 * 160 * 448];

// ---- bf16 mma.sync ----
__device__ __forceinline__ void mma16816(float& c0, float& c1, float& c2, float& c3,
                                         uns a0, uns a1, uns a2, uns a3,
                                         uns b0, uns b1) {
    asm volatile("mma.sync.aligned.m16n8k16.row.col.f32.bf16.bf16.f32 {%0,%1,%2,%3}, {%4,%5,%6,%7}, {%8,%9}, {%0,%1,%2,%3};" : "+f"(c0), "+f"(c1), "+f"(c2), "+f"(c3) : "r"(a0), "r"(a1), "r"(a2), "r"(a3), "r"(b0), "r"(b1));
}

__device__ __forceinline__ void split_pair(float x, float y, uns& hip, uns& lop) {
    uns ux = __float_as_uint(x);
    uns uy = __float_as_uint(y);
    uns hx = ux & 0xFFFF0000u;
    uns hy = uy & 0xFFFF0000u;
    float rx = x - __uint_as_float(hx);
    float ry = y - __uint_as_float(hy);
    hip = (hx >> 16) | (hy & 0xFFFF0000u);
    lop = (__float_as_uint(rx) >> 16) | (__float_as_uint(ry) & 0xFFFF0000u);
}

// ===================== pre-split kernels =====================
__global__ __launch_bounds__(512) void split_a(const float* __restrict__ A, int K,
                                               ush* __restrict__ H, ush* __restrict__ L) {
    const int total = TT * 224;   // uns units per buffer
    for (int i = blockIdx.x * 512 + threadIdx.x; i < total; i += gridDim.x * 512) {
        int row = i / 224;
        int kk = i - row * 224;
        int k = kk * 2;
        uns hip = 0u;
        uns lop = 0u;
        if (k < K) {
            float2 v = *(const float2*)(A + (size_t)row * K + k);
            split_pair(v.x, v.y, hip, lop);
        }
        ((uns*)H)[i] = hip;
        ((uns*)L)[i] = lop;
    }
}

__global__ __launch_bounds__(512) void split_w(const float* __restrict__ attn_W1,
                                               const float* __restrict__ sc_W1) {
    const int total = 4 * 160 * 224;
    for (int i = blockIdx.x * 512 + threadIdx.x; i < total; i += gridDim.x * 512) {
        int j = i / (160 * 224);
        int r = i - j * 160 * 224;
        int n = r / 224;
        int kk = r - n * 224;
        int k = kk * 2;
        const float* W;
        int K;
        if (j == 0) { W = attn_W1; K = 400; }
        else if (j == 1) { W = sc_W1; K = 400; }
        else if (j == 2) { W = sc_W1 + 60000; K = 400; }
        else { W = sc_W1 + 120000; K = 300; }
        uns hip = 0u;
        uns lop = 0u;
        if (n < 150 && k < K) {
            float v0 = W[k * 150 + n];
            float v1 = W[(k + 1) * 150 + n];
            split_pair(v0, v1, hip, lop);
        }
        ((uns*)g_WH)[i] = hip;
        ((uns*)g_WL)[i] = lop;
    }
}

// ===================== fused proj_mma: copy-only staging =====================
#define PJ_AH 0
#define PJ_AL 18432
#define PJ_BH 36864
#define PJ_BL 59904
#define PJ_SMEM 82944

__global__ __launch_bounds__(512, 1) void proj_mma(float* __restrict__ C0,
                                                   float* __restrict__ C1,
                                                   float* __restrict__ C2,
                                                   float* __restrict__ C3) {
    extern __shared__ __align__(16) char smc[];
    const int jid = blockIdx.y;
    const ush* __restrict__ AH = (jid == 3) ? g_eAH : g_sAH;
    const ush* __restrict__ AL = (jid == 3) ? g_eAL : g_sAL;
    float* __restrict__ C;
    if (jid == 0) C = C0;
    else if (jid == 1) C = C1;
    else if (jid == 2) C = C2;
    else C = C3;
    const int nt = (jid == 3) ? 5 : 7;   // covers k<320 / k<448 (zero padded)
    const int jbase = jid * 160 * 448;

    const int tid = threadIdx.x;
    const int m0 = blockIdx.x * 128;
    const int warp = tid >> 5;
    const int lane = tid & 31;
    const int gid = lane >> 2;
    const int tig = lane & 3;
    const int mw = warp >> 1;
    const int nh = warp & 1;

    float acc[10][4];
#pragma unroll
    for (int j = 0; j < 10; j++) {
#pragma unroll
        for (int q = 0; q < 4; q++) acc[j][q] = 0.f;
    }

    for (int t = 0; t < nt; t++) {
        const int k0 = t << 6;
        __syncthreads();
        // A: 128 rows x 8 float4 (64 ks) per buffer
        for (int idx = tid; idx < 1024; idx += 512) {
            int row = idx >> 3;
            int f = idx & 7;
            float4 vh = make_float4(0.f, 0.f, 0.f, 0.f);
            float4 vl = make_float4(0.f, 0.f, 0.f, 0.f);
            if (m0 + row < TT) {
                size_t so = (size_t)(m0 + row) * 448 + k0 + f * 8;
                vh = *(const float4*)(AH + so);
                vl = *(const float4*)(AL + so);
            }
            int d = (row * 72 + f * 8) * 2;
            *(float4*)(smc + PJ_AH + d) = vh;
            *(float4*)(smc + PJ_AL + d) = vl;
        }
        // B: 160 rows x 8 float4 per buffer
        for (int idx = tid; idx < 1280; idx += 512) {
            int n = idx >> 3;
            int f = idx & 7;
            size_t so = (size_t)jbase + n * 448 + k0 + f * 8;
            float4 vh = *(const float4*)(g_WH + so);
            float4 vl = *(const float4*)(g_WL + so);
            int d = (n * 72 + f * 8) * 2;
            *(float4*)(smc + PJ_BH + d) = vh;
            *(float4*)(smc + PJ_BL + d) = vl;
        }
        __syncthreads();

#pragma unroll
        for (int ks = 0; ks < 4; ks++) {
            int arow0 = (mw * 16 + gid) * 72;
            int acol = ks * 16 + tig * 2;
            uns ah0 = *(uns*)(smc + PJ_AH + (arow0 + acol) * 2);
            uns ah1 = *(uns*)(smc + PJ_AH + (arow0 + 8 * 72 + acol) * 2);
            uns ah2 = *(uns*)(smc + PJ_AH + (arow0 + acol + 8) * 2);
            uns ah3 = *(uns*)(smc + PJ_AH + (arow0 + 8 * 72 + acol + 8) * 2);
            uns al0 = *(uns*)(smc + PJ_AL + (arow0 + acol) * 2);
            uns al1 = *(uns*)(smc + PJ_AL + (arow0 + 8 * 72 + acol) * 2);
            uns al2 = *(uns*)(smc + PJ_AL + (arow0 + acol + 8) * 2);
            uns al3 = *(uns*)(smc + PJ_AL + (arow0 + 8 * 72 + acol + 8) * 2);
#pragma unroll
            for (int j = 0; j < 10; j++) {
                int n = (nh * 10 + j) * 8 + gid;
                int kc = ks * 16 + tig * 2;
                uns bh0 = *(uns*)(smc + PJ_BH + (n * 72 + kc) * 2);
                uns bh1 = *(uns*)(smc + PJ_BH + (n * 72 + kc + 8) * 2);
                uns bl0 = *(uns*)(smc + PJ_BL + (n * 72 + kc) * 2);
                uns bl1 = *(uns*)(smc + PJ_BL + (n * 72 + kc + 8) * 2);
                mma16816(acc[j][0], acc[j][1], acc[j][2], acc[j][3], ah0, ah1, ah2, ah3, bh0, bh1);
                mma16816(acc[j][0], acc[j][1], acc[j][2], acc[j][3], ah0, ah1, ah2, ah3, bl0, bl1);
                mma16816(acc[j][0], acc[j][1], acc[j][2], acc[j][3], al0, al1, al2, al3, bh0, bh1);
            }
        }
    }

    {
        int mA = m0 + mw * 16 + gid;
        int mB = mA + 8;
#pragma unroll
        for (int j = 0; j < 10; j++) {
            int col = nh * 80 + j * 8 + tig * 2;
            if (mA < TT) {
                float2 v;
                v.x = acc[j][0];
                v.y = acc[j][1];
                *(float2*)(C + (size_t)mA * LDP + col) = v;
            }
            if (mB < TT) {
                float2 v;
                v.x = acc[j][2];
                v.y = acc[j][3];
                *(float2*)(C + (size_t)mB * LDP + col) = v;
            }
        }
    }
}

// ===================== attn_tail (unchanged, passing) =====================
__global__ __launch_bounds__(512, 1) void attn_tail(
    const float* __restrict__ b1, const float* __restrict__ W2,
    const float* __restrict__ b2, const float* __restrict__ W3,
    const float* __restrict__ b3) {
    extern __shared__ __align__(16) float smf[];
    float* W2T = smf;
    float* W3s = W2T + 160 * 154;
    float* b2s = W3s + 160;
    float* h1s = b2s + 160;

    const int tid = threadIdx.x;
    for (int i = tid; i < 160 * 154; i += 512) W2T[i] = 0.f;
    if (tid < 160) {
        W3s[tid] = (tid < 150) ? W3[tid] : 0.f;
        b2s[tid] = (tid < 150) ? b2[tid] : 0.f;
    }
    __syncthreads();
    for (int i = tid; i < 22500; i += 512) {
        int k = i / 150;
        int j = i - k * 150;
        W2T[j * 154 + k] = W2[i];
    }

    const int t0 = blockIdx.x * 64;
    for (int idx = tid; idx < 64 * 150; idx += 512) {
        int t = idx / 150;
        int k = idx - t * 150;
        float v = 0.f;
        if (t0 + t < TT) v = fmaxf(g_Ha[(size_t)(t0 + t) * LDP + k] + b1[k], 0.f);
        h1s[t * 154 + k] = v;
    }
    __syncthreads();

    const int w = tid >> 5;
    const int lane = tid & 31;
    ull acc[4][5];
#pragma unroll
    for (int i = 0; i < 4; i++)
#pragma unroll
        for (int c = 0; c < 5; c++) acc[i][c] = 0ull;

#pragma unroll 5
    for (int kp = 0; kp < 75; kp++) {
        ull h2[4];
#pragma unroll
        for (int i = 0; i < 4; i++)
            h2[i] = *(const ull*)(h1s + (w * 4 + i) * 154 + 2 * kp);
#pragma unroll
        for (int c = 0; c < 5; c++) {
            ull b2v = *(const ull*)(W2T + (lane + 32 * c) * 154 + 2 * kp);
#pragma unroll
            for (int i = 0; i < 4; i++) fma2(acc[i][c], h2[i], b2v);
        }
    }
#pragma unroll
    for (int i = 0; i < 4; i++) {
        float p = 0.f;
#pragma unroll
        for (int c = 0; c < 5; c++) {
            int j = lane + 32 * c;
            if (j < 150) p += fmaxf(unpack_sum(acc[i][c]) + b2s[j], 0.f) * W3s[j];
        }
#pragma unroll
        for (int off = 16; off > 0; off >>= 1) p += __shfl_xor_sync(0xffffffffu, p, off);
        int t = w * 4 + i;
        if (lane == 0 && t0 + t < TT) g_logit[t0 + t] = p + b3[0];
    }
}

// ===================== span_score (unchanged from R14, passing) =====================
#define SP_W2H 0
#define SP_W2L 53760
#define SP_H1H 107520
#define SP_H1L 129024
#define SP_PES 150528
#define SP_WS  194328
#define SP_B2  196888
#define SP_W3  197528
#define SP_B1  198168
#define SP_PRT 198808
#define SP_SMEM 199832

__global__ __launch_bounds__(512, 1) void span_score(
    const float* __restrict__ b1, const float* __restrict__ W2,
    const float* __restrict__ b2, const float* __restrict__ W3,
    const float* __restrict__ b3, float* __restrict__ out, int totalTiles) {
    extern __shared__ __align__(16) char smc[];
    float* PEs = (float*)(smc + SP_PES);
    float* ws  = (float*)(smc + SP_WS);
    float* b2s = (float*)(smc + SP_B2);
    float* W3s = (float*)(smc + SP_W3);
    float* b1s = (float*)(smc + SP_B1);
    float* prt = (float*)(smc + SP_PRT);

    const int tid = threadIdx.x;
    const int warp = tid >> 5;
    const int lane = tid & 31;
    const int gid = lane >> 2;
    const int tig = lane & 3;
    const int mw = warp & 3;
    const int nq = warp >> 2;

    for (int i = tid; i < 13440; i += 512) {
        *(uns*)(smc + SP_W2H + i * 4) = 0u;
        *(uns*)(smc + SP_W2L + i * 4) = 0u;
    }
    if (tid < 160) {
        W3s[tid] = (tid < 150) ? W3[tid] : 0.f;
        b2s[tid] = (tid < 150) ? b2[tid] : 0.f;
        b1s[tid] = (tid < 150) ? b1[tid] : 0.f;
    }
    for (int i = tid; i < 64 * 18; i += 512) {
        int t = i / 18;
        int k = 150 + i - (i / 18) * 18;
        *(ush*)(smc + SP_H1H + (t * 168 + k) * 2) = 0;
        *(ush*)(smc + SP_H1L + (t * 168 + k) * 2) = 0;
    }
    __syncthreads();
    for (int i = tid; i < 22500; i += 512) {
        int k = i / 150;
        int j = i - k * 150;
        float v = W2[i];
        uns u = __float_as_uint(v);
        uns h = u & 0xFFFF0000u;
        float r = v - __uint_as_float(h);
        int boff = (j * 168 + k) * 2;
        *(ush*)(smc + SP_W2H + boff) = (ush)(h >> 16);
        *(ush*)(smc + SP_W2L + boff) = (ush)(__float_as_uint(r) >> 16);
    }
    const float bias3 = b3[0];
    const int myrow = tid >> 3;
    const int klane = (tid & 7) * 2;

    for (int tile = blockIdx.x; tile < totalTiles; tile += gridDim.x) {
        int n = 1;
        int loc = tile;
#pragma unroll
        for (int nn = 1; nn <= 10; nn++) {
            int tn = (TT - nn + 1 + 63) >> 6;
            if (loc < tn) { n = nn; break; }
            loc -= tn;
        }
        const int s0 = loc << 6;
        const int S = TT - n + 1;
        const int cnt = min(64, S - s0);

        __syncthreads();

        for (int idx = tid; idx < 73 * 75; idx += 512) {
            int r = idx / 75;
            int k2 = idx - r * 75;
            float2 v = make_float2(0.f, 0.f);
            if (s0 + r < TT) v = *(const float2*)(g_PE + (size_t)(s0 + r) * LDP + k2 * 2);
            *(float2*)(PEs + r * 150 + k2 * 2) = v;
        }
        if (tid < 64) {
            float l[10];
            if (tid < cnt) {
                int s = s0 + tid;
                float m = -1e30f;
                for (int j = 0; j < n; j++) { l[j] = g_logit[s + j]; m = fmaxf(m, l[j]); }
                float sum = 0.f;
                for (int j = 0; j < n; j++) { l[j] = expf(l[j] - m); sum += l[j]; }
                float inv = 1.f / sum;
#pragma unroll
                for (int j = 0; j < 10; j++) ws[tid * 10 + j] = (j < n) ? l[j] * inv : 0.f;
            } else {
#pragma unroll
                for (int j = 0; j < 10; j++) ws[tid * 10 + j] = 0.f;
            }
        }
        __syncthreads();

        {
            const int t = myrow;
            const bool valid = t < cnt;
            const int s = s0 + t;
            float wr[10];
#pragma unroll
            for (int j = 0; j < 10; j++) wr[j] = ws[t * 10 + j];
            const float* psrow = g_Ps + (size_t)s * LDP;
            const float* perow = g_Pe + (size_t)(s + n - 1) * LDP;
#pragma unroll
            for (int i = 0; i < 10; i++) {
                int k = klane + 16 * i;
                if (k < 150) {
                    float ax = 0.f;
                    float ay = 0.f;
                    if (valid) {
                        float2 p1 = *(const float2*)(psrow + k);
                        float2 p2 = *(const float2*)(perow + k);
                        float2 bb = *(const float2*)(b1s + k);
                        ax = p1.x + p2.x + bb.x;
                        ay = p1.y + p2.y + bb.y;
#pragma unroll
                        for (int j = 0; j < 10; j++) {
                            float2 pe = *(const float2*)(PEs + (t + j) * 150 + k);
                            ax = fmaf(wr[j], pe.x, ax);
                            ay = fmaf(wr[j], pe.y, ay);
                        }
                        ax = fmaxf(ax, 0.f);
                        ay = fmaxf(ay, 0.f);
                    }
                    uns hip;
                    uns lop;
                    split_pair(ax, ay, hip, lop);
                    int boff = (t * 168 + k) * 2;
                    *(uns*)(smc + SP_H1H + boff) = hip;
                    *(uns*)(smc + SP_H1L + boff) = lop;
                }
            }
        }
        __syncthreads();

        float acc[5][4];
#pragma unroll
        for (int j = 0; j < 5; j++) {
#pragma unroll
            for (int q = 0; q < 4; q++) acc[j][q] = 0.f;
        }
#pragma unroll
        for (int ks = 0; ks < 10; ks++) {
            int arow0 = (mw * 16 + gid) * 168;
            int acol = ks * 16 + tig * 2;
            uns ah0 = *(uns*)(smc + SP_H1H + (arow0 + acol) * 2);
            uns ah1 = *(uns*)(smc + SP_H1H + (arow0 + 8 * 168 + acol) * 2);
            uns ah2 = *(uns*)(smc + SP_H1H + (arow0 + acol + 8) * 2);
            uns ah3 = *(uns*)(smc + SP_H1H + (arow0 + 8 * 168 + acol + 8) * 2);
            uns al0 = *(uns*)(smc + SP_H1L + (arow0 + acol) * 2);
            uns al1 = *(uns*)(smc + SP_H1L + (arow0 + 8 * 168 + acol) * 2);
            uns al2 = *(uns*)(smc + SP_H1L + (arow0 + acol + 8) * 2);
            uns al3 = *(uns*)(smc + SP_H1L + (arow0 + 8 * 168 + acol + 8) * 2);
#pragma unroll
            for (int j = 0; j < 5; j++) {
                int nn = (nq * 5 + j) * 8 + gid;
                int kc = ks * 16 + tig * 2;
                uns bh0 = *(uns*)(smc + SP_W2H + (nn * 168 + kc) * 2);
                uns bh1 = *(uns*)(smc + SP_W2H + (nn * 168 + kc + 8) * 2);
                uns bl0 = *(uns*)(smc + SP_W2L + (nn * 168 + kc) * 2);
                uns bl1 = *(uns*)(smc + SP_W2L + (nn * 168 + kc + 8) * 2);
                mma16816(acc[j][0], acc[j][1], acc[j][2], acc[j][3], ah0, ah1, ah2, ah3, bh0, bh1);
                mma16816(acc[j][0], acc[j][1], acc[j][2], acc[j][3], ah0, ah1, ah2, ah3, bl0, bl1);
                mma16816(acc[j][0], acc[j][1], acc[j][2], acc[j][3], al0, al1, al2, al3, bh0, bh1);
            }
        }

        float pA = 0.f;
        float pB = 0.f;
#pragma unroll
        for (int j = 0; j < 5; j++) {
            int col = (nq * 5 + j) * 8 + tig * 2;
#pragma unroll
            for (int c = 0; c < 2; c++) {
                float w3v = W3s[col + c];
                float b2v = b2s[col + c];
                pA += fmaxf(acc[j][c] + b2v, 0.f) * w3v;
                pB += fmaxf(acc[j][2 + c] + b2v, 0.f) * w3v;
            }
        }
        pA += __shfl_xor_sync(0xffffffffu, pA, 1);
        pA += __shfl_xor_sync(0xffffffffu, pA, 2);
        pB += __shfl_xor_sync(0xffffffffu, pB, 1);
        pB += __shfl_xor_sync(0xffffffffu, pB, 2);
        if (tig == 0) {
            prt[(mw * 16 + gid) * 4 + nq] = pA;
            prt[(mw * 16 + gid + 8) * 4 + nq] = pB;
        }
        __syncthreads();

        if (tid < 64 && tid < cnt) {
            const int base = (n - 1) * TT - ((n - 1) * (n - 2)) / 2;
            float sum = prt[tid * 4] + prt[tid * 4 + 1] + prt[tid * 4 + 2] + prt[tid * 4 + 3];
            out[base + s0 + tid] = sum + bias3;
        }
    }
}

extern "C" void kernel_launch(void* const* d_in, const int* in_sizes, int n_in,
                              void* d_out, int out_size) {
    const float* embeds = (const float*)d_in[0];
    const float* states = (const float*)d_in[1];
    const float* attn_W1 = (const float*)d_in[2];
    const float* attn_b1 = (const float*)d_in[3];
    const float* attn_W2 = (const float*)d_in[4];
    const float* attn_b2 = (const float*)d_in[5];
    const float* attn_W3 = (const float*)d_in[6];
    const float* attn_b3 = (const float*)d_in[7];
    const float* sc_W1 = (const float*)d_in[8];
    const float* sc_b1 = (const float*)d_in[9];
    const float* sc_W2 = (const float*)d_in[10];
    const float* sc_b2 = (const float*)d_in[11];
    const float* sc_W3 = (const float*)d_in[12];
    const float* sc_b3 = (const float*)d_in[13];
    float* out = (float*)d_out;

    float* pHa;
    float* pPs;
    float* pPe;
    float* pPE;
    ush* pSAH;
    ush* pSAL;
    ush* pEAH;
    ush* pEAL;
    cudaGetSymbolAddress((void**)&pHa, g_Ha);
    cudaGetSymbolAddress((void**)&pPs, g_Ps);
    cudaGetSymbolAddress((void**)&pPe, g_Pe);
    cudaGetSymbolAddress((void**)&pPE, g_PE);
    cudaGetSymbolAddress((void**)&pSAH, g_sAH);
    cudaGetSymbolAddress((void**)&pSAL, g_sAL);
    cudaGetSymbolAddress((void**)&pEAH, g_eAH);
    cudaGetSymbolAddress((void**)&pEAL, g_eAL);

    const int attnSmem = (160 * 154 + 160 + 160 + 64 * 154) * 4;
    cudaFuncSetAttribute(proj_mma, cudaFuncAttributeMaxDynamicSharedMemorySize, PJ_SMEM);
    cudaFuncSetAttribute(attn_tail, cudaFuncAttributeMaxDynamicSharedMemorySize, attnSmem);
    cudaFuncSetAttribute(span_score, cudaFuncAttributeMaxDynamicSharedMemorySize, SP_SMEM);

    int totalTiles = 0;
    for (int nn = 1; nn <= 10; nn++) {
        totalTiles += (TT - nn + 1 + 63) >> 6;
    }

    split_a<<<1480, 512>>>(states, 400, pSAH, pSAL);
    split_a<<<1480, 512>>>(embeds, 300, pEAH, pEAL);
    split_w<<<280, 512>>>(attn_W1, sc_W1);
    dim3 projGrid(157, 4);
    proj_mma<<<projGrid, 512, PJ_SMEM>>>(pHa, pPs, pPe, pPE);
    attn_tail<<<313, 512, attnSmem>>>(attn_b1, attn_W2, attn_b2, attn_W3, attn_b3);
    span_score<<<148, 512, SP_SMEM>>>(sc_b1, sc_W2, sc_b2, sc_W3, sc_b3, out, totalTiles);
}